// round 13
// baseline (speedup 1.0000x reference)
#include <cuda_runtime.h>
#include <cuda_bf16.h>
#include <cstdint>
#include <cstddef>

// ---------------- problem constants ----------------
#define S_LEN   4096
#define D_DIM   2048
#define C_DIM   64
#define NC_CH   1024
#define TOPK_N  512
#define NH_N    16
#define DC_N    512
#define NHI_N   4
#define CI_N    64
#define NG_N    4
#define DG_N    512

#define NEG_INF (__int_as_float(0xff800000))

// ---------------- scratch ----------------
__device__ float g_ca[S_LEN * C_DIM];
__device__ float g_cb[S_LEN * C_DIM];
__device__ float g_za[S_LEN * C_DIM];
__device__ float g_zb[S_LEN * C_DIM];
__device__ float g_kc[NC_CH * C_DIM];
__device__ float g_cq[S_LEN * DC_N];
__device__ float g_qi[S_LEN * NHI_N * CI_N];
__device__ float g_hw[S_LEN * NHI_N];
__device__ float g_kp[NC_CH * CI_N];
__device__ float g_qf[S_LEN * NH_N * C_DIM];
__device__ int   g_ti[S_LEN * TOPK_N];
__device__ float g_ao[S_LEN * NH_N * C_DIM];
__device__ float g_gb[(size_t)S_LEN * NG_N * DG_N];

// ---------------- bf16 helpers ----------------
__device__ __forceinline__ uint32_t pack_bf16(float e0, float e1) {
  uint32_t d;
  asm("cvt.rn.bf16x2.f32 %0, %1, %2;" : "=r"(d) : "f"(e1), "f"(e0));
  return d;
}
__device__ __forceinline__ void split_pair(float a0, float a1, uint32_t& hp, uint32_t& lp) {
  hp = pack_bf16(a0, a1);
  float r0 = a0 - __uint_as_float(hp << 16);
  float r1 = a1 - __uint_as_float(hp & 0xffff0000u);
  lp = pack_bf16(r0, r1);
}
__device__ __forceinline__ void mma_bf16(float* c, const uint32_t* a, const uint32_t* b) {
  asm volatile(
      "mma.sync.aligned.m16n8k16.row.col.f32.bf16.bf16.f32 "
      "{%0,%1,%2,%3}, {%4,%5,%6,%7}, {%8,%9}, {%0,%1,%2,%3};"
      : "+f"(c[0]), "+f"(c[1]), "+f"(c[2]), "+f"(c[3])
      : "r"(a[0]), "r"(a[1]), "r"(a[2]), "r"(a[3]), "r"(b[0]), "r"(b[1]));
}

// ================= fp32 SGEMM body (R4-exact arithmetic) ================
__device__ __forceinline__ void sgemm_body(
    char* sm, const float* A, const float* B, float* Cc,
    int K, int lda, int ldb, int ldc, int bm, int bn) {
  float (*As)[8][128] = reinterpret_cast<float(*)[8][128]>(sm);
  float (*Bs)[8][132] = reinterpret_cast<float(*)[8][132]>(sm + 8192);
  const int tid = threadIdx.x;
  const int tx = tid & 15, ty = tid >> 4;
  const int arow = tid >> 1, acol = (tid & 1) * 4;
  const int brow = tid >> 5, bcol = (tid & 31) * 4;

  const float* Aptr = A + (size_t)(bm + arow) * lda + acol;
  const float* Bptr = B + (size_t)brow * ldb + bn + bcol;

  float acc[8][8];
#pragma unroll
  for (int i = 0; i < 8; i++)
#pragma unroll
    for (int j = 0; j < 8; j++) acc[i][j] = 0.f;

  {
    float4 av = *reinterpret_cast<const float4*>(Aptr);
    float4 bv = *reinterpret_cast<const float4*>(Bptr);
    As[0][acol + 0][arow] = av.x;
    As[0][acol + 1][arow] = av.y;
    As[0][acol + 2][arow] = av.z;
    As[0][acol + 3][arow] = av.w;
    Bs[0][brow][bcol + 0] = bv.x;
    Bs[0][brow][bcol + 1] = bv.y;
    Bs[0][brow][bcol + 2] = bv.z;
    Bs[0][brow][bcol + 3] = bv.w;
  }
  __syncthreads();

  int buf = 0;
  for (int k0 = 0; k0 < K; k0 += 8) {
    float4 av, bv;
    const bool more = (k0 + 8 < K);
    if (more) {
      av = *reinterpret_cast<const float4*>(Aptr + k0 + 8);
      bv = *reinterpret_cast<const float4*>(Bptr + (size_t)(k0 + 8) * ldb);
    }
#pragma unroll
    for (int kk = 0; kk < 8; kk++) {
      float a[8], b[8];
#pragma unroll
      for (int i = 0; i < 8; i++) a[i] = As[buf][kk][ty * 8 + i];
#pragma unroll
      for (int j = 0; j < 8; j++) b[j] = Bs[buf][kk][tx * 8 + j];
#pragma unroll
      for (int i = 0; i < 8; i++)
#pragma unroll
        for (int j = 0; j < 8; j++) acc[i][j] += a[i] * b[j];
    }
    if (more) {
      int nb = buf ^ 1;
      As[nb][acol + 0][arow] = av.x;
      As[nb][acol + 1][arow] = av.y;
      As[nb][acol + 2][arow] = av.z;
      As[nb][acol + 3][arow] = av.w;
      Bs[nb][brow][bcol + 0] = bv.x;
      Bs[nb][brow][bcol + 1] = bv.y;
      Bs[nb][brow][bcol + 2] = bv.z;
      Bs[nb][brow][bcol + 3] = bv.w;
      __syncthreads();
      buf = nb;
    }
  }

#pragma unroll
  for (int i = 0; i < 8; i++) {
    float* crow = Cc + (size_t)(bm + ty * 8 + i) * ldc + bn + tx * 8;
    *reinterpret_cast<float4*>(crow) = make_float4(acc[i][0], acc[i][1], acc[i][2], acc[i][3]);
    *reinterpret_cast<float4*>(crow + 4) = make_float4(acc[i][4], acc[i][5], acc[i][6], acc[i][7]);
  }
}

// ================= proj64 body; optional fused chunk-mean A ============
__device__ __forceinline__ float4 ld_mean4(const float* p) {
  float4 a = *reinterpret_cast<const float4*>(p);
  float4 b = *reinterpret_cast<const float4*>(p + D_DIM);
  float4 c = *reinterpret_cast<const float4*>(p + 2 * D_DIM);
  float4 d = *reinterpret_cast<const float4*>(p + 3 * D_DIM);
  return make_float4(0.25f * (((a.x + b.x) + c.x) + d.x),
                     0.25f * (((a.y + b.y) + c.y) + d.y),
                     0.25f * (((a.z + b.z) + c.z) + d.z),
                     0.25f * (((a.w + b.w) + c.w) + d.w));
}

__device__ __forceinline__ void proj64_body(
    char* sm, const float* A, const float* B, float* Cc, int bm, bool mean4) {
  float (*As)[128] = reinterpret_cast<float(*)[128]>(sm);
  float (*Bs)[68] = reinterpret_cast<float(*)[68]>(sm + 4096);
  const int tid = threadIdx.x;
  const int tx = tid & 15, ty = tid >> 4;
  const int arow = tid >> 1, acol = (tid & 1) * 4;
  const int brow = tid >> 4, bcol = (tid & 15) * 4;
  const bool bload = (tid < 128);

  const float* Aptr = mean4 ? (A + (size_t)(4 * (bm + arow)) * D_DIM + acol)
                            : (A + (size_t)(bm + arow) * D_DIM + acol);
  const float* Bptr = B + (size_t)brow * C_DIM + bcol;

  float acc[8][4];
#pragma unroll
  for (int i = 0; i < 8; i++)
#pragma unroll
    for (int j = 0; j < 4; j++) acc[i][j] = 0.f;

  float4 av = mean4 ? ld_mean4(Aptr) : *reinterpret_cast<const float4*>(Aptr);
  float4 bv = bload ? *reinterpret_cast<const float4*>(Bptr) : make_float4(0, 0, 0, 0);

  for (int k0 = 0; k0 < D_DIM; k0 += 8) {
    As[acol + 0][arow] = av.x;
    As[acol + 1][arow] = av.y;
    As[acol + 2][arow] = av.z;
    As[acol + 3][arow] = av.w;
    if (bload) {
      Bs[brow][bcol + 0] = bv.x;
      Bs[brow][bcol + 1] = bv.y;
      Bs[brow][bcol + 2] = bv.z;
      Bs[brow][bcol + 3] = bv.w;
    }
    __syncthreads();

    if (k0 + 8 < D_DIM) {
      av = mean4 ? ld_mean4(Aptr + k0 + 8) : *reinterpret_cast<const float4*>(Aptr + k0 + 8);
      if (bload) bv = *reinterpret_cast<const float4*>(Bptr + (size_t)(k0 + 8) * C_DIM);
    }

#pragma unroll
    for (int kk = 0; kk < 8; kk++) {
      float a[8], b[4];
#pragma unroll
      for (int i = 0; i < 8; i++) a[i] = As[kk][ty * 8 + i];
#pragma unroll
      for (int j = 0; j < 4; j++) b[j] = Bs[kk][tx * 4 + j];
#pragma unroll
      for (int i = 0; i < 8; i++)
#pragma unroll
        for (int j = 0; j < 4; j++) acc[i][j] += a[i] * b[j];
    }
    __syncthreads();
  }

#pragma unroll
  for (int i = 0; i < 8; i++) {
    float* crow = Cc + (size_t)(bm + ty * 8 + i) * C_DIM + tx * 4;
    *reinterpret_cast<float4*>(crow) = make_float4(acc[i][0], acc[i][1], acc[i][2], acc[i][3]);
  }
}

// ================= hw body =============================================
__device__ __forceinline__ void hw_body(const float* x, const float* w_w, int blk) {
  int warp_g = blk * 8 + (threadIdx.x >> 5);
  int lane = threadIdx.x & 31;
  const float4* wr = reinterpret_cast<const float4*>(w_w);
  for (int row = warp_g; row < S_LEN; row += 256) {
    const float4* xr = reinterpret_cast<const float4*>(x + (size_t)row * D_DIM);
    float d0 = 0.f, d1 = 0.f, d2 = 0.f, d3 = 0.f;
    for (int i = lane; i < D_DIM / 4; i += 32) {
      float4 xv = xr[i];
      float4 w0 = wr[i * 4 + 0];
      float4 w1 = wr[i * 4 + 1];
      float4 w2 = wr[i * 4 + 2];
      float4 w3 = wr[i * 4 + 3];
      d0 += xv.x * w0.x + xv.y * w1.x + xv.z * w2.x + xv.w * w3.x;
      d1 += xv.x * w0.y + xv.y * w1.y + xv.z * w2.y + xv.w * w3.y;
      d2 += xv.x * w0.z + xv.y * w1.z + xv.z * w2.z + xv.w * w3.z;
      d3 += xv.x * w0.w + xv.y * w1.w + xv.z * w2.w + xv.w * w3.w;
    }
#pragma unroll
    for (int off = 16; off > 0; off >>= 1) {
      d0 += __shfl_down_sync(0xffffffffu, d0, off);
      d1 += __shfl_down_sync(0xffffffffu, d1, off);
      d2 += __shfl_down_sync(0xffffffffu, d2, off);
      d3 += __shfl_down_sync(0xffffffffu, d3, off);
    }
    if (lane == 0) {
      g_hw[row * 4 + 0] = d0;
      g_hw[row * 4 + 1] = d1;
      g_hw[row * 4 + 2] = d2;
      g_hw[row * 4 + 3] = d3;
    }
  }
}

// ================= superA ==============================================
struct SuperAArgs {
  const float* x;
  const float* w_dq;
  const float* w_kva;
  const float* w_kvb;
  const float* w_za;
  const float* w_zb;
  const float* w_k;
  const float* w_w;
  float* cq;
  float* ca;
  float* cb;
  float* za;
  float* zb;
  float* kp;
};

__global__ __launch_bounds__(256, 2) void superA_kernel(SuperAArgs a) {
  __shared__ __align__(16) char sm[16640];
  int id = blockIdx.x;
  if (id < 128) {
    sgemm_body(sm, a.x, a.w_dq, a.cq, D_DIM, D_DIM, DC_N, DC_N,
               (id >> 2) * 128, (id & 3) * 128);
  } else if (id < 288) {
    int pid = id - 128;
    int mat = pid >> 5, by = pid & 31;
    int bm = by * 128;
    if (mat == 4) {
      if (bm >= NC_CH) return;
      proj64_body(sm, a.x, a.w_k, a.kp, bm, true);
    } else {
      const float* B = (mat == 0) ? a.w_kva : (mat == 1) ? a.w_kvb : (mat == 2) ? a.w_za : a.w_zb;
      float* C = (mat == 0) ? a.ca : (mat == 1) ? a.cb : (mat == 2) ? a.za : a.zb;
      proj64_body(sm, a.x, B, C, bm, false);
    }
  } else {
    hw_body(a.x, a.w_w, id - 288);
  }
}

// ================= tensor GEMM body (R9 bf16 3-term) ===================
__device__ __forceinline__ void tgemm_body(
    char* sm, const float* A, const float* B, float* Cc,
    int K, int lda, int ldb, int ldc, int bm, int bn) {
  uint32_t* Ah = reinterpret_cast<uint32_t*>(sm);
  uint32_t* Al = reinterpret_cast<uint32_t*>(sm + 12288);
  uint32_t* Bh = reinterpret_cast<uint32_t*>(sm + 24576);
  uint32_t* Bl = reinterpret_cast<uint32_t*>(sm + 33280);
#define AH(b, r, p) Ah[(b) * 1536 + (r) * 12 + (p)]
#define AL(b, r, p) Al[(b) * 1536 + (r) * 12 + (p)]
#define BH(b, r, c) Bh[(b) * 1088 + (r) * 136 + (c)]
#define BL(b, r, c) Bl[(b) * 1088 + (r) * 136 + (c)]

  const int tid = threadIdx.x;
  const int warp = tid >> 5, lane = tid & 31;
  const int wm = warp >> 2, wn = warp & 3;
  const int g = lane >> 2, t = lane & 3;

  const int arow = tid >> 1, akoff = (tid & 1) * 8;
  const int brp = tid >> 5, bcol = lane * 4;

  const float* Aptr = A + (size_t)(bm + arow) * lda + akoff;
  const float* Bptr0 = B + (size_t)(2 * brp) * ldb + bn + bcol;
  const float* Bptr1 = Bptr0 + ldb;

  float acc[4][4][4];
#pragma unroll
  for (int i = 0; i < 4; i++)
#pragma unroll
    for (int j = 0; j < 4; j++)
#pragma unroll
      for (int r = 0; r < 4; r++) acc[i][j][r] = 0.f;

  float4 av0 = *reinterpret_cast<const float4*>(Aptr);
  float4 av1 = *reinterpret_cast<const float4*>(Aptr + 4);
  float4 bv0 = *reinterpret_cast<const float4*>(Bptr0);
  float4 bv1 = *reinterpret_cast<const float4*>(Bptr1);
  {
    uint32_t h[4], l[4];
    split_pair(av0.x, av0.y, h[0], l[0]);
    split_pair(av0.z, av0.w, h[1], l[1]);
    split_pair(av1.x, av1.y, h[2], l[2]);
    split_pair(av1.z, av1.w, h[3], l[3]);
    int ac = akoff >> 1;
    *reinterpret_cast<uint4*>(&AH(0, arow, ac)) = make_uint4(h[0], h[1], h[2], h[3]);
    *reinterpret_cast<uint4*>(&AL(0, arow, ac)) = make_uint4(l[0], l[1], l[2], l[3]);
    uint32_t bh[4], bl[4];
    split_pair(bv0.x, bv1.x, bh[0], bl[0]);
    split_pair(bv0.y, bv1.y, bh[1], bl[1]);
    split_pair(bv0.z, bv1.z, bh[2], bl[2]);
    split_pair(bv0.w, bv1.w, bh[3], bl[3]);
    *reinterpret_cast<uint4*>(&BH(0, brp, bcol)) = make_uint4(bh[0], bh[1], bh[2], bh[3]);
    *reinterpret_cast<uint4*>(&BL(0, brp, bcol)) = make_uint4(bl[0], bl[1], bl[2], bl[3]);
  }
  __syncthreads();

  int buf = 0;
  for (int k0 = 0; k0 < K; k0 += 16) {
    const bool more = (k0 + 16 < K);
    if (more) {
      av0 = *reinterpret_cast<const float4*>(Aptr + k0 + 16);
      av1 = *reinterpret_cast<const float4*>(Aptr + k0 + 20);
      bv0 = *reinterpret_cast<const float4*>(Bptr0 + (size_t)(k0 + 16) * ldb);
      bv1 = *reinterpret_cast<const float4*>(Bptr1 + (size_t)(k0 + 16) * ldb);
    }

    {
      uint32_t bhf[4][2], blf[4][2];
#pragma unroll
      for (int ni = 0; ni < 4; ni++) {
        int colB = wn * 32 + ni * 8 + g;
        bhf[ni][0] = BH(buf, t, colB);
        bhf[ni][1] = BH(buf, t + 4, colB);
        blf[ni][0] = BL(buf, t, colB);
        blf[ni][1] = BL(buf, t + 4, colB);
      }
#pragma unroll
      for (int mi = 0; mi < 4; mi++) {
        int rowA = wm * 64 + mi * 16 + g;
        uint32_t ah[4], al[4];
        ah[0] = AH(buf, rowA, t);
        ah[1] = AH(buf, rowA + 8, t);
        ah[2] = AH(buf, rowA, t + 4);
        ah[3] = AH(buf, rowA + 8, t + 4);
        al[0] = AL(buf, rowA, t);
        al[1] = AL(buf, rowA + 8, t);
        al[2] = AL(buf, rowA, t + 4);
        al[3] = AL(buf, rowA + 8, t + 4);
#pragma unroll
        for (int ni = 0; ni < 4; ni++) mma_bf16(acc[mi][ni], ah, bhf[ni]);
#pragma unroll
        for (int ni = 0; ni < 4; ni++) mma_bf16(acc[mi][ni], ah, blf[ni]);
#pragma unroll
        for (int ni = 0; ni < 4; ni++) mma_bf16(acc[mi][ni], al, bhf[ni]);
      }
    }

    if (more) {
      int nb = buf ^ 1;
      uint32_t h[4], l[4];
      split_pair(av0.x, av0.y, h[0], l[0]);
      split_pair(av0.z, av0.w, h[1], l[1]);
      split_pair(av1.x, av1.y, h[2], l[2]);
      split_pair(av1.z, av1.w, h[3], l[3]);
      int ac = akoff >> 1;
      *reinterpret_cast<uint4*>(&AH(nb, arow, ac)) = make_uint4(h[0], h[1], h[2], h[3]);
      *reinterpret_cast<uint4*>(&AL(nb, arow, ac)) = make_uint4(l[0], l[1], l[2], l[3]);
      uint32_t bh[4], bl[4];
      split_pair(bv0.x, bv1.x, bh[0], bl[0]);
      split_pair(bv0.y, bv1.y, bh[1], bl[1]);
      split_pair(bv0.z, bv1.z, bh[2], bl[2]);
      split_pair(bv0.w, bv1.w, bh[3], bl[3]);
      *reinterpret_cast<uint4*>(&BH(nb, brp, bcol)) = make_uint4(bh[0], bh[1], bh[2], bh[3]);
      *reinterpret_cast<uint4*>(&BL(nb, brp, bcol)) = make_uint4(bl[0], bl[1], bl[2], bl[3]);
      __syncthreads();
      buf = nb;
    }
  }

#pragma unroll
  for (int mi = 0; mi < 4; mi++) {
    int row0 = bm + wm * 64 + mi * 16 + g;
#pragma unroll
    for (int ni = 0; ni < 4; ni++) {
      int col = bn + wn * 32 + ni * 8 + 2 * t;
      *reinterpret_cast<float2*>(Cc + (size_t)row0 * ldc + col) =
          make_float2(acc[mi][ni][0], acc[mi][ni][1]);
      *reinterpret_cast<float2*>(Cc + (size_t)(row0 + 8) * ldc + col) =
          make_float2(acc[mi][ni][2], acc[mi][ni][3]);
    }
  }
#undef AH
#undef AL
#undef BH
#undef BL
}

__global__ __launch_bounds__(256) void tgemm_kernel(
    const float* __restrict__ A, const float* __restrict__ B,
    float* __restrict__ Cc, int K, int lda, int ldb, int ldc,
    long sA, long sB, long sC) {
  __shared__ __align__(16) char sm[41984];
  tgemm_body(sm, A + (long)blockIdx.z * sA, B + (long)blockIdx.z * sB,
             Cc + (long)blockIdx.z * sC, K, lda, ldb, ldc,
             blockIdx.y * 128, blockIdx.x * 128);
}

// ================= superC: q_i fp32 GEMM || w_uq tensor GEMM ============
__global__ __launch_bounds__(256) void superC_kernel(
    const float* __restrict__ cq, const float* __restrict__ w_iuq,
    const float* __restrict__ w_uq, float* __restrict__ qi, float* __restrict__ qf) {
  __shared__ __align__(16) char sm[41984];
  int id = blockIdx.x;
  if (id < 64) {
    sgemm_body(sm, cq, w_iuq, qi, DC_N, DC_N, NHI_N * CI_N, NHI_N * CI_N,
               (id >> 1) * 128, (id & 1) * 128);
  } else {
    int tid2 = id - 64;
    tgemm_body(sm, cq, w_uq, qf, DC_N, DC_N, NH_N * C_DIM, NH_N * C_DIM,
               (tid2 >> 3) * 128, (tid2 & 7) * 128);
  }
}

// ------------- compression softmax + LayerNorm --------------------------
__global__ void compress_kernel(const float* __restrict__ b_a,
                                const float* __restrict__ b_b,
                                const float* __restrict__ kvn_w,
                                const float* __restrict__ kvn_b) {
  int nc = blockIdx.x;
  int c = threadIdx.x;  // 64
  float lg[8], val[8];
#pragma unroll
  for (int m = 0; m < 4; m++) {
    int cur = (nc * 4 + m) * 64 + c;
    lg[4 + m] = g_za[cur] + b_a[m * 64 + c];
    val[4 + m] = g_ca[cur];
    if (nc > 0) {
      int prev = ((nc - 1) * 4 + m) * 64 + c;
      lg[m] = g_zb[prev] + b_b[m * 64 + c];
      val[m] = g_cb[prev];
    } else {
      lg[m] = -1e30f + b_b[m * 64 + c];
      val[m] = 0.f;
    }
  }
  float mx = lg[0];
#pragma unroll
  for (int i = 1; i < 8; i++) mx = fmaxf(mx, lg[i]);
  float se = 0.f, comp = 0.f;
#pragma unroll
  for (int i = 0; i < 8; i++) {
    float e = expf(lg[i] - mx);
    se += e;
    comp += e * val[i];
  }
  comp /= se;

  __shared__ float red[64];
  red[c] = comp;
  __syncthreads();
  for (int off = 32; off > 0; off >>= 1) {
    if (c < off) red[c] += red[c + off];
    __syncthreads();
  }
  float mu = red[0] * (1.f / 64.f);
  __syncthreads();
  float dv = comp - mu;
  red[c] = dv * dv;
  __syncthreads();
  for (int off = 32; off > 0; off >>= 1) {
    if (c < off) red[c] += red[c + off];
    __syncthreads();
  }
  float var = red[0] * (1.f / 64.f);
  g_kc[nc * 64 + c] = dv * rsqrtf(var + 1e-6f) * kvn_w[c] + kvn_b[c];
}

// ------------- per-(s,h) LayerNorm then RoPE ----------------------------
__global__ void qln_rope_kernel(const float* __restrict__ qn_w,
                                const float* __restrict__ qn_b) {
  int s = blockIdx.x;
  int c = threadIdx.x;  // 64
  int h = threadIdx.y;  // 16
  float v = g_qf[(size_t)s * 1024 + h * 64 + c];
  __shared__ float red[16][64];
  __shared__ float lnb[16][65];
  red[h][c] = v;
  __syncthreads();
  for (int off = 32; off > 0; off >>= 1) {
    if (c < off) red[h][c] += red[h][c + off];
    __syncthreads();
  }
  float mu = red[h][0] * (1.f / 64.f);
  __syncthreads();
  float dv = v - mu;
  red[h][c] = dv * dv;
  __syncthreads();
  for (int off = 32; off > 0; off >>= 1) {
    if (c < off) red[h][c] += red[h][c + off];
    __syncthreads();
  }
  float var = red[h][0] * (1.f / 64.f);
  float ln = dv * rsqrtf(var + 1e-6f) * qn_w[c] + qn_b[c];
  lnb[h][c] = ln;
  __syncthreads();
  float outv;
  if (c < 32) {
    outv = ln;
  } else {
    int j = (c - 32) >> 1;
    float inv = exp2f(-(float)j * 0.830482023722f);  // 10000^(-j/16)
    float ang = (float)s * inv;
    float cs = cosf(ang), sn = sinf(ang);
    float x0 = lnb[h][32 + 2 * j], x1 = lnb[h][32 + 2 * j + 1];
    outv = ((c & 1) == 0) ? (x0 * cs - x1 * sn) : (x0 * sn + x1 * cs);
  }
  g_qf[(size_t)s * 1024 + h * 64 + c] = outv;
}

// ------------- FUSED indexer scores + exact top-512 ---------------------
// Scores computed with instruction-identical arithmetic to R12 iscore,
// straight into the sort arrays (no g_is round-trip).
__global__ __launch_bounds__(512) void iscore_topk_kernel() {
  int s = blockIdx.x, tid = threadIdx.x;  // 512
  __shared__ float qs[256];
  __shared__ float ws[4];
  __shared__ float v[1024];
  __shared__ int ix[1024];
  if (tid < 256) qs[tid] = g_qi[(size_t)s * 256 + tid];
  if (tid >= 256 && tid < 260) ws[tid - 256] = g_hw[s * 4 + (tid - 256)];
  __syncthreads();
  const float4* qs4 = reinterpret_cast<const float4*>(qs);
  for (int k = tid; k < NC_CH; k += 512) {
    const float4* kr = reinterpret_cast<const float4*>(g_kp + k * 64);
    float d0 = 0.f, d1 = 0.f, d2 = 0.f, d3 = 0.f;
#pragma unroll
    for (int c4 = 0; c4 < 16; c4++) {
      float4 kv = kr[c4];
      float4 q0 = qs4[c4];
      float4 q1 = qs4[16 + c4];
      float4 q2 = qs4[32 + c4];
      float4 q3 = qs4[48 + c4];
      d0 += q0.x * kv.x + q0.y * kv.y + q0.z * kv.z + q0.w * kv.w;
      d1 += q1.x * kv.x + q1.y * kv.y + q1.z * kv.z + q1.w * kv.w;
      d2 += q2.x * kv.x + q2.y * kv.y + q2.z * kv.z + q2.w * kv.w;
      d3 += q3.x * kv.x + q3.y * kv.y + q3.z * kv.z + q3.w * kv.w;
    }
    float sc = fmaxf(d0, 0.f) * ws[0] + fmaxf(d1, 0.f) * ws[1] +
               fmaxf(d2, 0.f) * ws[2] + fmaxf(d3, 0.f) * ws[3];
    v[k] = (k < s) ? sc : NEG_INF;
    ix[k] = k;
  }
  __syncthreads();
  for (int k = 2; k <= 1024; k <<= 1) {
    for (int j = k >> 1; j > 0; j >>= 1) {
      for (int t = tid; t < 1024; t += 512) {
        int p = t ^ j;
        if (p > t) {
          float va = v[t], vb = v[p];
          int ia = ix[t], ib = ix[p];
          bool before = (va > vb) || (va == vb && ia < ib);
          bool dir = ((t & k) == 0);
          if (before != dir) {
            v[t] = vb; v[p] = va;
            ix[t] = ib; ix[p] = ia;
          }
        }
      }
      __syncthreads();
    }
  }
  g_ti[(size_t)s * 512 + tid] = ix[tid];
}

// ------------- gathered sparse attention (512 threads) ------------------
__global__ __launch_bounds__(512) void attn_kernel(const float* __restrict__ sink) {
  const int s = blockIdx.x, tid = threadIdx.x;  // 512
  __shared__ float qs[1024];
  __shared__ float Ks[128][68];
  __shared__ float ew[16][128];
  __shared__ float denom[16];

  qs[tid] = g_qf[(size_t)s * 1024 + tid];
  qs[tid + 512] = g_qf[(size_t)s * 1024 + tid + 512];
  if (tid < 16) denom[tid] = __expf(sink[tid]);
  __syncthreads();

  const int c = tid & 63, g2 = tid >> 6;  // 8 head-groups of 2
  float acc0 = 0.f, acc1 = 0.f;
  const float4* qs4 = reinterpret_cast<const float4*>(qs);
  const int* trow = g_ti + (size_t)s * 512;

  for (int qtr = 0; qtr < 4; qtr++) {
    if (qtr) __syncthreads();

    // stage 128 gathered K rows: 4 threads per row, 4 float4 each
    {
      int j = tid >> 2, p = tid & 3;
      int ck = trow[qtr * 128 + j];
      const float4* src = reinterpret_cast<const float4*>(g_kc + ck * 64);
      float4* dst = reinterpret_cast<float4*>(&Ks[j][0]);
#pragma unroll
      for (int q = 0; q < 4; q++) dst[p + 4 * q] = src[p + 4 * q];
    }
    __syncthreads();

    // phase 1: scores -> exp; 4 threads per chunk, 4 heads each
    {
      int kk = tid >> 2, hh = (tid & 3) * 4;
      int ck = trow[qtr * 128 + kk];
      bool valid = (s < ck * 4);
      const float4* kr = reinterpret_cast<const float4*>(&Ks[kk][0]);
      float d[4];
#pragma unroll
      for (int h = 0; h < 4; h++) d[h] = 0.f;
#pragma unroll
      for (int c4 = 0; c4 < 16; c4++) {
        float4 kv = kr[c4];
#pragma unroll
        for (int h = 0; h < 4; h++) {
          float4 qv = qs4[(hh + h) * 16 + c4];
          d[h] += qv.x * kv.x + qv.y * kv.y + qv.z * kv.z + qv.w * kv.w;
        }
      }
#pragma unroll
      for (int h = 0; h < 4; h++) ew[hh + h][kk] = valid ? __expf(d[h] * 0.125f) : 0.f;
    }
    __syncthreads();

    // phase 2: denominators — one warp per head
    {
      int h = tid >> 5, seg = tid & 31;
      float4 v0 = *reinterpret_cast<const float4*>(&ew[h][seg * 4]);
      float p = v0.x + v0.y + v0.z + v0.w;
#pragma unroll
      for (int off = 16; off > 0; off >>= 1) p += __shfl_down_sync(0xffffffffu, p, off);
      if (seg == 0) denom[h] += p;
    }

    // phase 3: AV, 2 heads per thread
    for (int k4 = 0; k4 < 128; k4 += 4) {
      float4 e0 = *reinterpret_cast<const float4*>(&ew[g2][k4]);
      float4 e1 = *reinterpret_cast<const float4*>(&ew[g2 + 8][k4]);
      float kv0 = Ks[k4 + 0][c];
      float kv1 = Ks[k4 + 1][c];
      float kv2 = Ks[k4 + 2][c];
      float kv3 = Ks[k4 + 3][c];
      acc0 += e0.x * kv0 + e0.y * kv1 + e0.z * kv2 + e0.w * kv3;
      acc1 += e1.x * kv0 + e1.y * kv1 + e1.z * kv2 + e1.w * kv3;
    }
  }
  __syncthreads();

  g_ao[(size_t)s * 1024 + g2 * 64 + c] = acc0 / denom[g2];
  g_ao[(size_t)s * 1024 + (g2 + 8) * 64 + c] = acc1 / denom[g2 + 8];
}

// ---------------------------- launcher ----------------------------------
extern "C" void kernel_launch(void* const* d_in, const int* in_sizes, int n_in,
                              void* d_out, int out_size) {
  (void)in_sizes; (void)n_in; (void)out_size;
  const float* x      = (const float*)d_in[0];
  const float* w_kva  = (const float*)d_in[1];
  const float* w_kvb  = (const float*)d_in[2];
  const float* w_za   = (const float*)d_in[3];
  const float* w_zb   = (const float*)d_in[4];
  const float* b_a    = (const float*)d_in[5];
  const float* b_b    = (const float*)d_in[6];
  const float* w_dq   = (const float*)d_in[7];
  const float* w_iuq  = (const float*)d_in[8];
  const float* w_w    = (const float*)d_in[9];
  const float* w_k    = (const float*)d_in[10];
  const float* w_uq   = (const float*)d_in[11];
  const float* o_down = (const float*)d_in[12];
  const float* o_up   = (const float*)d_in[13];
  const float* kvn_w  = (const float*)d_in[14];
  const float* kvn_b  = (const float*)d_in[15];
  const float* qn_w   = (const float*)d_in[16];
  const float* qn_b   = (const float*)d_in[17];
  const float* sink   = (const float*)d_in[18];
  float* out = (float*)d_out;

  void *p_ca, *p_cb, *p_za, *p_zb, *p_cq, *p_qi, *p_kp, *p_qf, *p_ao, *p_gb;
  cudaGetSymbolAddress(&p_ca, g_ca);
  cudaGetSymbolAddress(&p_cb, g_cb);
  cudaGetSymbolAddress(&p_za, g_za);
  cudaGetSymbolAddress(&p_zb, g_zb);
  cudaGetSymbolAddress(&p_cq, g_cq);
  cudaGetSymbolAddress(&p_qi, g_qi);
  cudaGetSymbolAddress(&p_kp, g_kp);
  cudaGetSymbolAddress(&p_qf, g_qf);
  cudaGetSymbolAddress(&p_ao, g_ao);
  cudaGetSymbolAddress(&p_gb, g_gb);

  // superA: c_q GEMM (128) || projections incl. fused chunk-mean (160) || hw (32)
  SuperAArgs sa;
  sa.x = x;
  sa.w_dq = w_dq;
  sa.w_kva = w_kva;
  sa.w_kvb = w_kvb;
  sa.w_za = w_za;
  sa.w_zb = w_zb;
  sa.w_k = w_k;
  sa.w_w = w_w;
  sa.cq = (float*)p_cq;
  sa.ca = (float*)p_ca;
  sa.cb = (float*)p_cb;
  sa.za = (float*)p_za;
  sa.zb = (float*)p_zb;
  sa.kp = (float*)p_kp;
  superA_kernel<<<320, 256>>>(sa);

  // chunk compression + LN(kc)
  compress_kernel<<<NC_CH, 64>>>(b_a, b_b, kvn_w, kvn_b);

  // superC: q_i fp32 GEMM (64) || w_uq tensor GEMM (256)
  superC_kernel<<<320, 256>>>((const float*)p_cq, w_iuq, w_uq, (float*)p_qi, (float*)p_qf);

  // LN+rope on q; fused indexer scoring + exact top-k
  qln_rope_kernel<<<S_LEN, dim3(64, 16)>>>(qn_w, qn_b);
  iscore_topk_kernel<<<S_LEN, 512>>>();

  // sparse attention over top-k compressed chunks
  attn_kernel<<<S_LEN, 512>>>(sink);

  // grouped o_down: batched tensor GEMM
  tgemm_kernel<<<dim3(DG_N / 128, S_LEN / 128, NG_N), 256>>>(
      (const float*)p_ao, o_down, (float*)p_gb,
      256, NH_N * C_DIM, DG_N, NG_N * DG_N,
      /*sA=*/256, /*sB=*/(long)256 * DG_N, /*sC=*/DG_N);

  // o_up (tensor)
  tgemm_kernel<<<dim3(D_DIM / 128, S_LEN / 128, 1), 256>>>(
      (const float*)p_gb, o_up, out,
      NG_N * DG_N, NG_N * DG_N, D_DIM, D_DIM, 0, 0, 0);
}

// round 14
// speedup vs baseline: 1.5405x; 1.5405x over previous
#include <cuda_runtime.h>
#include <cuda_bf16.h>
#include <cstdint>
#include <cstddef>

// ---------------- problem constants ----------------
#define S_LEN   4096
#define D_DIM   2048
#define C_DIM   64
#define NC_CH   1024
#define TOPK_N  512
#define NH_N    16
#define DC_N    512
#define NHI_N   4
#define CI_N    64
#define NG_N    4
#define DG_N    512

#define NEG_INF (__int_as_float(0xff800000))

// ---------------- scratch ----------------
__device__ float g_ca[S_LEN * C_DIM];
__device__ float g_cb[S_LEN * C_DIM];
__device__ float g_za[S_LEN * C_DIM];
__device__ float g_zb[S_LEN * C_DIM];
__device__ float g_kc[NC_CH * C_DIM];
__device__ float g_cq[S_LEN * DC_N];
__device__ float g_qi[S_LEN * NHI_N * CI_N];
__device__ float g_hw[S_LEN * NHI_N];
__device__ float g_kp[NC_CH * CI_N];
__device__ float g_qf[S_LEN * NH_N * C_DIM];
__device__ float g_is[(size_t)S_LEN * NC_CH];
__device__ int   g_ti[S_LEN * TOPK_N];
__device__ float g_ao[S_LEN * NH_N * C_DIM];
__device__ float g_gb[(size_t)S_LEN * NG_N * DG_N];

// ---------------- bf16 helpers ----------------
__device__ __forceinline__ uint32_t pack_bf16(float e0, float e1) {
  uint32_t d;
  asm("cvt.rn.bf16x2.f32 %0, %1, %2;" : "=r"(d) : "f"(e1), "f"(e0));
  return d;
}
__device__ __forceinline__ void split_pair(float a0, float a1, uint32_t& hp, uint32_t& lp) {
  hp = pack_bf16(a0, a1);
  float r0 = a0 - __uint_as_float(hp << 16);
  float r1 = a1 - __uint_as_float(hp & 0xffff0000u);
  lp = pack_bf16(r0, r1);
}
__device__ __forceinline__ void mma_bf16(float* c, const uint32_t* a, const uint32_t* b) {
  asm volatile(
      "mma.sync.aligned.m16n8k16.row.col.f32.bf16.bf16.f32 "
      "{%0,%1,%2,%3}, {%4,%5,%6,%7}, {%8,%9}, {%0,%1,%2,%3};"
      : "+f"(c[0]), "+f"(c[1]), "+f"(c[2]), "+f"(c[3])
      : "r"(a[0]), "r"(a[1]), "r"(a[2]), "r"(a[3]), "r"(b[0]), "r"(b[1]));
}

// ================= fp32 SGEMM body (R4-exact arithmetic) ================
__device__ __forceinline__ void sgemm_body(
    char* sm, const float* A, const float* B, float* Cc,
    int K, int lda, int ldb, int ldc, int bm, int bn) {
  float (*As)[8][128] = reinterpret_cast<float(*)[8][128]>(sm);
  float (*Bs)[8][132] = reinterpret_cast<float(*)[8][132]>(sm + 8192);
  const int tid = threadIdx.x;
  const int tx = tid & 15, ty = tid >> 4;
  const int arow = tid >> 1, acol = (tid & 1) * 4;
  const int brow = tid >> 5, bcol = (tid & 31) * 4;

  const float* Aptr = A + (size_t)(bm + arow) * lda + acol;
  const float* Bptr = B + (size_t)brow * ldb + bn + bcol;

  float acc[8][8];
#pragma unroll
  for (int i = 0; i < 8; i++)
#pragma unroll
    for (int j = 0; j < 8; j++) acc[i][j] = 0.f;

  {
    float4 av = *reinterpret_cast<const float4*>(Aptr);
    float4 bv = *reinterpret_cast<const float4*>(Bptr);
    As[0][acol + 0][arow] = av.x;
    As[0][acol + 1][arow] = av.y;
    As[0][acol + 2][arow] = av.z;
    As[0][acol + 3][arow] = av.w;
    Bs[0][brow][bcol + 0] = bv.x;
    Bs[0][brow][bcol + 1] = bv.y;
    Bs[0][brow][bcol + 2] = bv.z;
    Bs[0][brow][bcol + 3] = bv.w;
  }
  __syncthreads();

  int buf = 0;
  for (int k0 = 0; k0 < K; k0 += 8) {
    float4 av, bv;
    const bool more = (k0 + 8 < K);
    if (more) {
      av = *reinterpret_cast<const float4*>(Aptr + k0 + 8);
      bv = *reinterpret_cast<const float4*>(Bptr + (size_t)(k0 + 8) * ldb);
    }
#pragma unroll
    for (int kk = 0; kk < 8; kk++) {
      float a[8], b[8];
#pragma unroll
      for (int i = 0; i < 8; i++) a[i] = As[buf][kk][ty * 8 + i];
#pragma unroll
      for (int j = 0; j < 8; j++) b[j] = Bs[buf][kk][tx * 8 + j];
#pragma unroll
      for (int i = 0; i < 8; i++)
#pragma unroll
        for (int j = 0; j < 8; j++) acc[i][j] += a[i] * b[j];
    }
    if (more) {
      int nb = buf ^ 1;
      As[nb][acol + 0][arow] = av.x;
      As[nb][acol + 1][arow] = av.y;
      As[nb][acol + 2][arow] = av.z;
      As[nb][acol + 3][arow] = av.w;
      Bs[nb][brow][bcol + 0] = bv.x;
      Bs[nb][brow][bcol + 1] = bv.y;
      Bs[nb][brow][bcol + 2] = bv.z;
      Bs[nb][brow][bcol + 3] = bv.w;
      __syncthreads();
      buf = nb;
    }
  }

#pragma unroll
  for (int i = 0; i < 8; i++) {
    float* crow = Cc + (size_t)(bm + ty * 8 + i) * ldc + bn + tx * 8;
    *reinterpret_cast<float4*>(crow) = make_float4(acc[i][0], acc[i][1], acc[i][2], acc[i][3]);
    *reinterpret_cast<float4*>(crow + 4) = make_float4(acc[i][4], acc[i][5], acc[i][6], acc[i][7]);
  }
}

// ================= proj64 body; optional fused chunk-mean A ============
__device__ __forceinline__ float4 ld_mean4(const float* p) {
  float4 a = *reinterpret_cast<const float4*>(p);
  float4 b = *reinterpret_cast<const float4*>(p + D_DIM);
  float4 c = *reinterpret_cast<const float4*>(p + 2 * D_DIM);
  float4 d = *reinterpret_cast<const float4*>(p + 3 * D_DIM);
  return make_float4(0.25f * (((a.x + b.x) + c.x) + d.x),
                     0.25f * (((a.y + b.y) + c.y) + d.y),
                     0.25f * (((a.z + b.z) + c.z) + d.z),
                     0.25f * (((a.w + b.w) + c.w) + d.w));
}

__device__ __forceinline__ void proj64_body(
    char* sm, const float* A, const float* B, float* Cc, int bm, bool mean4) {
  float (*As)[128] = reinterpret_cast<float(*)[128]>(sm);
  float (*Bs)[68] = reinterpret_cast<float(*)[68]>(sm + 4096);
  const int tid = threadIdx.x;
  const int tx = tid & 15, ty = tid >> 4;
  const int arow = tid >> 1, acol = (tid & 1) * 4;
  const int brow = tid >> 4, bcol = (tid & 15) * 4;
  const bool bload = (tid < 128);

  const float* Aptr = mean4 ? (A + (size_t)(4 * (bm + arow)) * D_DIM + acol)
                            : (A + (size_t)(bm + arow) * D_DIM + acol);
  const float* Bptr = B + (size_t)brow * C_DIM + bcol;

  float acc[8][4];
#pragma unroll
  for (int i = 0; i < 8; i++)
#pragma unroll
    for (int j = 0; j < 4; j++) acc[i][j] = 0.f;

  float4 av = mean4 ? ld_mean4(Aptr) : *reinterpret_cast<const float4*>(Aptr);
  float4 bv = bload ? *reinterpret_cast<const float4*>(Bptr) : make_float4(0, 0, 0, 0);

  for (int k0 = 0; k0 < D_DIM; k0 += 8) {
    As[acol + 0][arow] = av.x;
    As[acol + 1][arow] = av.y;
    As[acol + 2][arow] = av.z;
    As[acol + 3][arow] = av.w;
    if (bload) {
      Bs[brow][bcol + 0] = bv.x;
      Bs[brow][bcol + 1] = bv.y;
      Bs[brow][bcol + 2] = bv.z;
      Bs[brow][bcol + 3] = bv.w;
    }
    __syncthreads();

    if (k0 + 8 < D_DIM) {
      av = mean4 ? ld_mean4(Aptr + k0 + 8) : *reinterpret_cast<const float4*>(Aptr + k0 + 8);
      if (bload) bv = *reinterpret_cast<const float4*>(Bptr + (size_t)(k0 + 8) * C_DIM);
    }

#pragma unroll
    for (int kk = 0; kk < 8; kk++) {
      float a[8], b[4];
#pragma unroll
      for (int i = 0; i < 8; i++) a[i] = As[kk][ty * 8 + i];
#pragma unroll
      for (int j = 0; j < 4; j++) b[j] = Bs[kk][tx * 4 + j];
#pragma unroll
      for (int i = 0; i < 8; i++)
#pragma unroll
        for (int j = 0; j < 4; j++) acc[i][j] += a[i] * b[j];
    }
    __syncthreads();
  }

#pragma unroll
  for (int i = 0; i < 8; i++) {
    float* crow = Cc + (size_t)(bm + ty * 8 + i) * C_DIM + tx * 4;
    *reinterpret_cast<float4*>(crow) = make_float4(acc[i][0], acc[i][1], acc[i][2], acc[i][3]);
  }
}

// ================= hw body =============================================
__device__ __forceinline__ void hw_body(const float* x, const float* w_w, int blk) {
  int warp_g = blk * 8 + (threadIdx.x >> 5);
  int lane = threadIdx.x & 31;
  const float4* wr = reinterpret_cast<const float4*>(w_w);
  for (int row = warp_g; row < S_LEN; row += 256) {
    const float4* xr = reinterpret_cast<const float4*>(x + (size_t)row * D_DIM);
    float d0 = 0.f, d1 = 0.f, d2 = 0.f, d3 = 0.f;
    for (int i = lane; i < D_DIM / 4; i += 32) {
      float4 xv = xr[i];
      float4 w0 = wr[i * 4 + 0];
      float4 w1 = wr[i * 4 + 1];
      float4 w2 = wr[i * 4 + 2];
      float4 w3 = wr[i * 4 + 3];
      d0 += xv.x * w0.x + xv.y * w1.x + xv.z * w2.x + xv.w * w3.x;
      d1 += xv.x * w0.y + xv.y * w1.y + xv.z * w2.y + xv.w * w3.y;
      d2 += xv.x * w0.z + xv.y * w1.z + xv.z * w2.z + xv.w * w3.z;
      d3 += xv.x * w0.w + xv.y * w1.w + xv.z * w2.w + xv.w * w3.w;
    }
#pragma unroll
    for (int off = 16; off > 0; off >>= 1) {
      d0 += __shfl_down_sync(0xffffffffu, d0, off);
      d1 += __shfl_down_sync(0xffffffffu, d1, off);
      d2 += __shfl_down_sync(0xffffffffu, d2, off);
      d3 += __shfl_down_sync(0xffffffffu, d3, off);
    }
    if (lane == 0) {
      g_hw[row * 4 + 0] = d0;
      g_hw[row * 4 + 1] = d1;
      g_hw[row * 4 + 2] = d2;
      g_hw[row * 4 + 3] = d3;
    }
  }
}

// ================= superA ==============================================
struct SuperAArgs {
  const float* x;
  const float* w_dq;
  const float* w_kva;
  const float* w_kvb;
  const float* w_za;
  const float* w_zb;
  const float* w_k;
  const float* w_w;
  float* cq;
  float* ca;
  float* cb;
  float* za;
  float* zb;
  float* kp;
};

__global__ __launch_bounds__(256, 2) void superA_kernel(SuperAArgs a) {
  __shared__ __align__(16) char sm[16640];
  int id = blockIdx.x;
  if (id < 128) {
    sgemm_body(sm, a.x, a.w_dq, a.cq, D_DIM, D_DIM, DC_N, DC_N,
               (id >> 2) * 128, (id & 3) * 128);
  } else if (id < 288) {
    int pid = id - 128;
    int mat = pid >> 5, by = pid & 31;
    int bm = by * 128;
    if (mat == 4) {
      if (bm >= NC_CH) return;
      proj64_body(sm, a.x, a.w_k, a.kp, bm, true);
    } else {
      const float* B = (mat == 0) ? a.w_kva : (mat == 1) ? a.w_kvb : (mat == 2) ? a.w_za : a.w_zb;
      float* C = (mat == 0) ? a.ca : (mat == 1) ? a.cb : (mat == 2) ? a.za : a.zb;
      proj64_body(sm, a.x, B, C, bm, false);
    }
  } else {
    hw_body(a.x, a.w_w, id - 288);
  }
}

// ================= tensor GEMM body (R9 bf16 3-term) ===================
__device__ __forceinline__ void tgemm_body(
    char* sm, const float* A, const float* B, float* Cc,
    int K, int lda, int ldb, int ldc, int bm, int bn) {
  uint32_t* Ah = reinterpret_cast<uint32_t*>(sm);
  uint32_t* Al = reinterpret_cast<uint32_t*>(sm + 12288);
  uint32_t* Bh = reinterpret_cast<uint32_t*>(sm + 24576);
  uint32_t* Bl = reinterpret_cast<uint32_t*>(sm + 33280);
#define AH(b, r, p) Ah[(b) * 1536 + (r) * 12 + (p)]
#define AL(b, r, p) Al[(b) * 1536 + (r) * 12 + (p)]
#define BH(b, r, c) Bh[(b) * 1088 + (r) * 136 + (c)]
#define BL(b, r, c) Bl[(b) * 1088 + (r) * 136 + (c)]

  const int tid = threadIdx.x;
  const int warp = tid >> 5, lane = tid & 31;
  const int wm = warp >> 2, wn = warp & 3;
  const int g = lane >> 2, t = lane & 3;

  const int arow = tid >> 1, akoff = (tid & 1) * 8;
  const int brp = tid >> 5, bcol = lane * 4;

  const float* Aptr = A + (size_t)(bm + arow) * lda + akoff;
  const float* Bptr0 = B + (size_t)(2 * brp) * ldb + bn + bcol;
  const float* Bptr1 = Bptr0 + ldb;

  float acc[4][4][4];
#pragma unroll
  for (int i = 0; i < 4; i++)
#pragma unroll
    for (int j = 0; j < 4; j++)
#pragma unroll
      for (int r = 0; r < 4; r++) acc[i][j][r] = 0.f;

  float4 av0 = *reinterpret_cast<const float4*>(Aptr);
  float4 av1 = *reinterpret_cast<const float4*>(Aptr + 4);
  float4 bv0 = *reinterpret_cast<const float4*>(Bptr0);
  float4 bv1 = *reinterpret_cast<const float4*>(Bptr1);
  {
    uint32_t h[4], l[4];
    split_pair(av0.x, av0.y, h[0], l[0]);
    split_pair(av0.z, av0.w, h[1], l[1]);
    split_pair(av1.x, av1.y, h[2], l[2]);
    split_pair(av1.z, av1.w, h[3], l[3]);
    int ac = akoff >> 1;
    *reinterpret_cast<uint4*>(&AH(0, arow, ac)) = make_uint4(h[0], h[1], h[2], h[3]);
    *reinterpret_cast<uint4*>(&AL(0, arow, ac)) = make_uint4(l[0], l[1], l[2], l[3]);
    uint32_t bh[4], bl[4];
    split_pair(bv0.x, bv1.x, bh[0], bl[0]);
    split_pair(bv0.y, bv1.y, bh[1], bl[1]);
    split_pair(bv0.z, bv1.z, bh[2], bl[2]);
    split_pair(bv0.w, bv1.w, bh[3], bl[3]);
    *reinterpret_cast<uint4*>(&BH(0, brp, bcol)) = make_uint4(bh[0], bh[1], bh[2], bh[3]);
    *reinterpret_cast<uint4*>(&BL(0, brp, bcol)) = make_uint4(bl[0], bl[1], bl[2], bl[3]);
  }
  __syncthreads();

  int buf = 0;
  for (int k0 = 0; k0 < K; k0 += 16) {
    const bool more = (k0 + 16 < K);
    if (more) {
      av0 = *reinterpret_cast<const float4*>(Aptr + k0 + 16);
      av1 = *reinterpret_cast<const float4*>(Aptr + k0 + 20);
      bv0 = *reinterpret_cast<const float4*>(Bptr0 + (size_t)(k0 + 16) * ldb);
      bv1 = *reinterpret_cast<const float4*>(Bptr1 + (size_t)(k0 + 16) * ldb);
    }

    {
      uint32_t bhf[4][2], blf[4][2];
#pragma unroll
      for (int ni = 0; ni < 4; ni++) {
        int colB = wn * 32 + ni * 8 + g;
        bhf[ni][0] = BH(buf, t, colB);
        bhf[ni][1] = BH(buf, t + 4, colB);
        blf[ni][0] = BL(buf, t, colB);
        blf[ni][1] = BL(buf, t + 4, colB);
      }
#pragma unroll
      for (int mi = 0; mi < 4; mi++) {
        int rowA = wm * 64 + mi * 16 + g;
        uint32_t ah[4], al[4];
        ah[0] = AH(buf, rowA, t);
        ah[1] = AH(buf, rowA + 8, t);
        ah[2] = AH(buf, rowA, t + 4);
        ah[3] = AH(buf, rowA + 8, t + 4);
        al[0] = AL(buf, rowA, t);
        al[1] = AL(buf, rowA + 8, t);
        al[2] = AL(buf, rowA, t + 4);
        al[3] = AL(buf, rowA + 8, t + 4);
#pragma unroll
        for (int ni = 0; ni < 4; ni++) mma_bf16(acc[mi][ni], ah, bhf[ni]);
#pragma unroll
        for (int ni = 0; ni < 4; ni++) mma_bf16(acc[mi][ni], ah, blf[ni]);
#pragma unroll
        for (int ni = 0; ni < 4; ni++) mma_bf16(acc[mi][ni], al, bhf[ni]);
      }
    }

    if (more) {
      int nb = buf ^ 1;
      uint32_t h[4], l[4];
      split_pair(av0.x, av0.y, h[0], l[0]);
      split_pair(av0.z, av0.w, h[1], l[1]);
      split_pair(av1.x, av1.y, h[2], l[2]);
      split_pair(av1.z, av1.w, h[3], l[3]);
      int ac = akoff >> 1;
      *reinterpret_cast<uint4*>(&AH(nb, arow, ac)) = make_uint4(h[0], h[1], h[2], h[3]);
      *reinterpret_cast<uint4*>(&AL(nb, arow, ac)) = make_uint4(l[0], l[1], l[2], l[3]);
      uint32_t bh[4], bl[4];
      split_pair(bv0.x, bv1.x, bh[0], bl[0]);
      split_pair(bv0.y, bv1.y, bh[1], bl[1]);
      split_pair(bv0.z, bv1.z, bh[2], bl[2]);
      split_pair(bv0.w, bv1.w, bh[3], bl[3]);
      *reinterpret_cast<uint4*>(&BH(nb, brp, bcol)) = make_uint4(bh[0], bh[1], bh[2], bh[3]);
      *reinterpret_cast<uint4*>(&BL(nb, brp, bcol)) = make_uint4(bl[0], bl[1], bl[2], bl[3]);
      __syncthreads();
      buf = nb;
    }
  }

#pragma unroll
  for (int mi = 0; mi < 4; mi++) {
    int row0 = bm + wm * 64 + mi * 16 + g;
#pragma unroll
    for (int ni = 0; ni < 4; ni++) {
      int col = bn + wn * 32 + ni * 8 + 2 * t;
      *reinterpret_cast<float2*>(Cc + (size_t)row0 * ldc + col) =
          make_float2(acc[mi][ni][0], acc[mi][ni][1]);
      *reinterpret_cast<float2*>(Cc + (size_t)(row0 + 8) * ldc + col) =
          make_float2(acc[mi][ni][2], acc[mi][ni][3]);
    }
  }
#undef AH
#undef AL
#undef BH
#undef BL
}

__global__ __launch_bounds__(256) void tgemm_kernel(
    const float* __restrict__ A, const float* __restrict__ B,
    float* __restrict__ Cc, int K, int lda, int ldb, int ldc,
    long sA, long sB, long sC) {
  __shared__ __align__(16) char sm[41984];
  tgemm_body(sm, A + (long)blockIdx.z * sA, B + (long)blockIdx.z * sB,
             Cc + (long)blockIdx.z * sC, K, lda, ldb, ldc,
             blockIdx.y * 128, blockIdx.x * 128);
}

// ======= compress body: 4 groups of 64 threads, R12-identical math ======
__device__ __forceinline__ void compress_body(
    char* sm, int nc, int grp, int c,
    const float* b_a, const float* b_b,
    const float* kvn_w, const float* kvn_b) {
  float (*red)[64] = reinterpret_cast<float(*)[64]>(sm);
  float lg[8], val[8];
#pragma unroll
  for (int m = 0; m < 4; m++) {
    int cur = (nc * 4 + m) * 64 + c;
    lg[4 + m] = g_za[cur] + b_a[m * 64 + c];
    val[4 + m] = g_ca[cur];
    if (nc > 0) {
      int prev = ((nc - 1) * 4 + m) * 64 + c;
      lg[m] = g_zb[prev] + b_b[m * 64 + c];
      val[m] = g_cb[prev];
    } else {
      lg[m] = -1e30f + b_b[m * 64 + c];
      val[m] = 0.f;
    }
  }
  float mx = lg[0];
#pragma unroll
  for (int i = 1; i < 8; i++) mx = fmaxf(mx, lg[i]);
  float se = 0.f, comp = 0.f;
#pragma unroll
  for (int i = 0; i < 8; i++) {
    float e = expf(lg[i] - mx);
    se += e;
    comp += e * val[i];
  }
  comp /= se;

  red[grp][c] = comp;
  __syncthreads();
  for (int off = 32; off > 0; off >>= 1) {
    if (c < off) red[grp][c] += red[grp][c + off];
    __syncthreads();
  }
  float mu = red[grp][0] * (1.f / 64.f);
  __syncthreads();
  float dv = comp - mu;
  red[grp][c] = dv * dv;
  __syncthreads();
  for (int off = 32; off > 0; off >>= 1) {
    if (c < off) red[grp][c] += red[grp][c + off];
    __syncthreads();
  }
  float var = red[grp][0] * (1.f / 64.f);
  g_kc[nc * 64 + c] = dv * rsqrtf(var + 1e-6f) * kvn_w[c] + kvn_b[c];
}

// ====== superC: q_i fp32 GEMM || w_uq tensor GEMM || compress ==========
__global__ __launch_bounds__(256) void superC_kernel(
    const float* __restrict__ cq, const float* __restrict__ w_iuq,
    const float* __restrict__ w_uq, float* __restrict__ qi, float* __restrict__ qf,
    const float* __restrict__ b_a, const float* __restrict__ b_b,
    const float* __restrict__ kvn_w, const float* __restrict__ kvn_b) {
  __shared__ __align__(16) char sm[41984];
  int id = blockIdx.x;
  if (id < 64) {
    sgemm_body(sm, cq, w_iuq, qi, DC_N, DC_N, NHI_N * CI_N, NHI_N * CI_N,
               (id >> 1) * 128, (id & 1) * 128);
  } else if (id < 320) {
    int tid2 = id - 64;
    tgemm_body(sm, cq, w_uq, qf, DC_N, DC_N, NH_N * C_DIM, NH_N * C_DIM,
               (tid2 >> 3) * 128, (tid2 & 7) * 128);
  } else {
    int tid = threadIdx.x;
    int nc = (id - 320) * 4 + (tid >> 6);
    compress_body(sm, nc, tid >> 6, tid & 63, b_a, b_b, kvn_w, kvn_b);
  }
}

// ===== fused qln_rope || iscore (independent; R12-identical bodies) =====
__global__ __launch_bounds__(1024) void qln_iscore_kernel(
    const float* __restrict__ qn_w, const float* __restrict__ qn_b) {
  int tid = threadIdx.x;
  if (blockIdx.x < S_LEN) {
    // ---- qln_rope body (c = tid&63, h = tid>>6; identical to R12) ----
    int s = blockIdx.x;
    int c = tid & 63;
    int h = tid >> 6;
    __shared__ float red[16][64];
    __shared__ float lnb[16][65];
    float v = g_qf[(size_t)s * 1024 + h * 64 + c];
    red[h][c] = v;
    __syncthreads();
    for (int off = 32; off > 0; off >>= 1) {
      if (c < off) red[h][c] += red[h][c + off];
      __syncthreads();
    }
    float mu = red[h][0] * (1.f / 64.f);
    __syncthreads();
    float dv = v - mu;
    red[h][c] = dv * dv;
    __syncthreads();
    for (int off = 32; off > 0; off >>= 1) {
      if (c < off) red[h][c] += red[h][c + off];
      __syncthreads();
    }
    float var = red[h][0] * (1.f / 64.f);
    float ln = dv * rsqrtf(var + 1e-6f) * qn_w[c] + qn_b[c];
    lnb[h][c] = ln;
    __syncthreads();
    float outv;
    if (c < 32) {
      outv = ln;
    } else {
      int j = (c - 32) >> 1;
      float inv = exp2f(-(float)j * 0.830482023722f);  // 10000^(-j/16)
      float ang = (float)s * inv;
      float cs = cosf(ang), sn = sinf(ang);
      float x0 = lnb[h][32 + 2 * j], x1 = lnb[h][32 + 2 * j + 1];
      outv = ((c & 1) == 0) ? (x0 * cs - x1 * sn) : (x0 * sn + x1 * cs);
    }
    g_qf[(size_t)s * 1024 + h * 64 + c] = outv;
  } else {
    // ---- iscore body (1 chunk/thread; dot sequence identical to R12) --
    int s = blockIdx.x - S_LEN;
    __shared__ float qs[256];
    __shared__ float ws[4];
    if (tid < 256) qs[tid] = g_qi[(size_t)s * 256 + tid];
    if (tid >= 256 && tid < 260) ws[tid - 256] = g_hw[s * 4 + (tid - 256)];
    __syncthreads();
    const float4* qs4 = reinterpret_cast<const float4*>(qs);
    int k = tid;  // 1024 chunks, 1024 threads
    const float4* kr = reinterpret_cast<const float4*>(g_kp + k * 64);
    float d0 = 0.f, d1 = 0.f, d2 = 0.f, d3 = 0.f;
#pragma unroll
    for (int c4 = 0; c4 < 16; c4++) {
      float4 kv = kr[c4];
      float4 q0 = qs4[c4];
      float4 q1 = qs4[16 + c4];
      float4 q2 = qs4[32 + c4];
      float4 q3 = qs4[48 + c4];
      d0 += q0.x * kv.x + q0.y * kv.y + q0.z * kv.z + q0.w * kv.w;
      d1 += q1.x * kv.x + q1.y * kv.y + q1.z * kv.z + q1.w * kv.w;
      d2 += q2.x * kv.x + q2.y * kv.y + q2.z * kv.z + q2.w * kv.w;
      d3 += q3.x * kv.x + q3.y * kv.y + q3.z * kv.z + q3.w * kv.w;
    }
    float sc = fmaxf(d0, 0.f) * ws[0] + fmaxf(d1, 0.f) * ws[1] +
               fmaxf(d2, 0.f) * ws[2] + fmaxf(d3, 0.f) * ws[3];
    g_is[(size_t)s * NC_CH + k] = (k < s) ? sc : NEG_INF;
  }
}

// ------------- exact top-512: bitonic sort (R12 verbatim) ---------------
__global__ __launch_bounds__(512) void topk_kernel() {
  int s = blockIdx.x, tid = threadIdx.x;  // 512
  __shared__ float v[1024];
  __shared__ int ix[1024];
  v[tid] = g_is[(size_t)s * 1024 + tid];
  ix[tid] = tid;
  v[tid + 512] = g_is[(size_t)s * 1024 + tid + 512];
  ix[tid + 512] = tid + 512;
  __syncthreads();
  for (int k = 2; k <= 1024; k <<= 1) {
    for (int j = k >> 1; j > 0; j >>= 1) {
      for (int t = tid; t < 1024; t += 512) {
        int p = t ^ j;
        if (p > t) {
          float va = v[t], vb = v[p];
          int ia = ix[t], ib = ix[p];
          bool before = (va > vb) || (va == vb && ia < ib);
          bool dir = ((t & k) == 0);
          if (before != dir) {
            v[t] = vb; v[p] = va;
            ix[t] = ib; ix[p] = ia;
          }
        }
      }
      __syncthreads();
    }
  }
  g_ti[(size_t)s * 512 + tid] = ix[tid];
}

// ------------- gathered sparse attention (R12 verbatim, 256 thr) --------
__global__ __launch_bounds__(256) void attn_kernel(const float* __restrict__ sink) {
  const int s = blockIdx.x, tid = threadIdx.x;  // 256
  __shared__ float qs[1024];
  __shared__ float Ks[128][68];
  __shared__ float ew[16][128];
  __shared__ float denom[16];

#pragma unroll
  for (int i = 0; i < 4; i++) qs[tid + 256 * i] = g_qf[(size_t)s * 1024 + tid + 256 * i];
  if (tid < 16) denom[tid] = __expf(sink[tid]);
  __syncthreads();

  const int c = tid & 63, g = tid >> 6;
  float acc0 = 0.f, acc1 = 0.f, acc2 = 0.f, acc3 = 0.f;
  const float4* qs4 = reinterpret_cast<const float4*>(qs);
  const int* trow = g_ti + (size_t)s * 512;

  for (int qtr = 0; qtr < 4; qtr++) {
    if (qtr) __syncthreads();

    {
      int j = tid >> 1, p = tid & 1;
      int ck = trow[qtr * 128 + j];
      const float4* src = reinterpret_cast<const float4*>(g_kc + ck * 64);
      float4* dst = reinterpret_cast<float4*>(&Ks[j][0]);
#pragma unroll
      for (int q = 0; q < 8; q++) dst[p + 2 * q] = src[p + 2 * q];
    }
    __syncthreads();

    {
      int kk = tid >> 1, hh = (tid & 1) * 8;
      int ck = trow[qtr * 128 + kk];
      bool valid = (s < ck * 4);
      const float4* kr = reinterpret_cast<const float4*>(&Ks[kk][0]);
      float d[8];
#pragma unroll
      for (int h = 0; h < 8; h++) d[h] = 0.f;
#pragma unroll
      for (int c4 = 0; c4 < 16; c4++) {
        float4 kv = kr[c4];
#pragma unroll
        for (int h = 0; h < 8; h++) {
          float4 qv = qs4[(hh + h) * 16 + c4];
          d[h] += qv.x * kv.x + qv.y * kv.y + qv.z * kv.z + qv.w * kv.w;
        }
      }
#pragma unroll
      for (int h = 0; h < 8; h++) ew[hh + h][kk] = valid ? __expf(d[h] * 0.125f) : 0.f;
    }
    __syncthreads();

    {
      int h = tid >> 4, seg = tid & 15;
      float4 v0 = *reinterpret_cast<const float4*>(&ew[h][seg * 8]);
      float4 v1 = *reinterpret_cast<const float4*>(&ew[h][seg * 8 + 4]);
      float p = v0.x + v0.y + v0.z + v0.w + v1.x + v1.y + v1.z + v1.w;
#pragma unroll
      for (int off = 8; off > 0; off >>= 1) p += __shfl_down_sync(0xffffffffu, p, off);
      if (seg == 0) denom[h] += p;
    }

    for (int k4 = 0; k4 < 128; k4 += 4) {
      float4 e0 = *reinterpret_cast<const float4*>(&ew[g][k4]);
      float4 e1 = *reinterpret_cast<const float4*>(&ew[g + 4][k4]);
      float4 e2 = *reinterpret_cast<const float4*>(&ew[g + 8][k4]);
      float4 e3 = *reinterpret_cast<const float4*>(&ew[g + 12][k4]);
      float kv0 = Ks[k4 + 0][c];
      float kv1 = Ks[k4 + 1][c];
      float kv2 = Ks[k4 + 2][c];
      float kv3 = Ks[k4 + 3][c];
      acc0 += e0.x * kv0 + e0.y * kv1 + e0.z * kv2 + e0.w * kv3;
      acc1 += e1.x * kv0 + e1.y * kv1 + e1.z * kv2 + e1.w * kv3;
      acc2 += e2.x * kv0 + e2.y * kv1 + e2.z * kv2 + e2.w * kv3;
      acc3 += e3.x * kv0 + e3.y * kv1 + e3.z * kv2 + e3.w * kv3;
    }
  }
  __syncthreads();

  g_ao[(size_t)s * 1024 + (g) * 64 + c] = acc0 / denom[g];
  g_ao[(size_t)s * 1024 + (g + 4) * 64 + c] = acc1 / denom[g + 4];
  g_ao[(size_t)s * 1024 + (g + 8) * 64 + c] = acc2 / denom[g + 8];
  g_ao[(size_t)s * 1024 + (g + 12) * 64 + c] = acc3 / denom[g + 12];
}

// ---------------------------- launcher ----------------------------------
extern "C" void kernel_launch(void* const* d_in, const int* in_sizes, int n_in,
                              void* d_out, int out_size) {
  (void)in_sizes; (void)n_in; (void)out_size;
  const float* x      = (const float*)d_in[0];
  const float* w_kva  = (const float*)d_in[1];
  const float* w_kvb  = (const float*)d_in[2];
  const float* w_za   = (const float*)d_in[3];
  const float* w_zb   = (const float*)d_in[4];
  const float* b_a    = (const float*)d_in[5];
  const float* b_b    = (const float*)d_in[6];
  const float* w_dq   = (const float*)d_in[7];
  const float* w_iuq  = (const float*)d_in[8];
  const float* w_w    = (const float*)d_in[9];
  const float* w_k    = (const float*)d_in[10];
  const float* w_uq   = (const float*)d_in[11];
  const float* o_down = (const float*)d_in[12];
  const float* o_up   = (const float*)d_in[13];
  const float* kvn_w  = (const float*)d_in[14];
  const float* kvn_b  = (const float*)d_in[15];
  const float* qn_w   = (const float*)d_in[16];
  const float* qn_b   = (const float*)d_in[17];
  const float* sink   = (const float*)d_in[18];
  float* out = (float*)d_out;

  void *p_ca, *p_cb, *p_za, *p_zb, *p_cq, *p_qi, *p_kp, *p_qf, *p_ao, *p_gb;
  cudaGetSymbolAddress(&p_ca, g_ca);
  cudaGetSymbolAddress(&p_cb, g_cb);
  cudaGetSymbolAddress(&p_za, g_za);
  cudaGetSymbolAddress(&p_zb, g_zb);
  cudaGetSymbolAddress(&p_cq, g_cq);
  cudaGetSymbolAddress(&p_qi, g_qi);
  cudaGetSymbolAddress(&p_kp, g_kp);
  cudaGetSymbolAddress(&p_qf, g_qf);
  cudaGetSymbolAddress(&p_ao, g_ao);
  cudaGetSymbolAddress(&p_gb, g_gb);

  // superA: c_q GEMM (128) || projections incl. fused chunk-mean (160) || hw (32)
  SuperAArgs sa;
  sa.x = x;
  sa.w_dq = w_dq;
  sa.w_kva = w_kva;
  sa.w_kvb = w_kvb;
  sa.w_za = w_za;
  sa.w_zb = w_zb;
  sa.w_k = w_k;
  sa.w_w = w_w;
  sa.cq = (float*)p_cq;
  sa.ca = (float*)p_ca;
  sa.cb = (float*)p_cb;
  sa.za = (float*)p_za;
  sa.zb = (float*)p_zb;
  sa.kp = (float*)p_kp;
  superA_kernel<<<320, 256>>>(sa);

  // superC: q_i fp32 GEMM (64) || w_uq tensor GEMM (256) || compress (256)
  superC_kernel<<<576, 256>>>((const float*)p_cq, w_iuq, w_uq, (float*)p_qi, (float*)p_qf,
                              b_a, b_b, kvn_w, kvn_b);

  // qln_rope || iscore (independent), then exact top-k
  qln_iscore_kernel<<<2 * S_LEN, 1024>>>(qn_w, qn_b);
  topk_kernel<<<S_LEN, 512>>>();

  // sparse attention over top-k compressed chunks (R12 kernel)
  attn_kernel<<<S_LEN, 256>>>(sink);

  // grouped o_down: batched tensor GEMM
  tgemm_kernel<<<dim3(DG_N / 128, S_LEN / 128, NG_N), 256>>>(
      (const float*)p_ao, o_down, (float*)p_gb,
      256, NH_N * C_DIM, DG_N, NG_N * DG_N,
      /*sA=*/256, /*sB=*/(long)256 * DG_N, /*sC=*/DG_N);

  // o_up (tensor)
  tgemm_kernel<<<dim3(D_DIM / 128, S_LEN / 128, 1), 256>>>(
      (const float*)p_gb, o_up, out,
      NG_N * DG_N, NG_N * DG_N, D_DIM, D_DIM, 0, 0, 0);
}

// round 15
// speedup vs baseline: 1.5915x; 1.0331x over previous
#include <cuda_runtime.h>
#include <cuda_bf16.h>
#include <cstdint>
#include <cstddef>

// ---------------- problem constants ----------------
#define S_LEN   4096
#define D_DIM   2048
#define C_DIM   64
#define NC_CH   1024
#define TOPK_N  512
#define NH_N    16
#define DC_N    512
#define NHI_N   4
#define CI_N    64
#define NG_N    4
#define DG_N    512

#define NEG_INF (__int_as_float(0xff800000))

// ---------------- scratch ----------------
__device__ float g_ca[S_LEN * C_DIM];
__device__ float g_cb[S_LEN * C_DIM];
__device__ float g_za[S_LEN * C_DIM];
__device__ float g_zb[S_LEN * C_DIM];
__device__ float g_kc[NC_CH * C_DIM];
__device__ float g_cq[S_LEN * DC_N];
__device__ float g_qi[S_LEN * NHI_N * CI_N];
__device__ float g_hw[S_LEN * NHI_N];
__device__ float g_kp[NC_CH * CI_N];
__device__ float g_qf[S_LEN * NH_N * C_DIM];
__device__ float g_is[(size_t)S_LEN * NC_CH];
__device__ int   g_ti[S_LEN * TOPK_N];
__device__ float g_ao[S_LEN * NH_N * C_DIM];
__device__ float g_gb[(size_t)S_LEN * NG_N * DG_N];

// ---------------- bf16 helpers ----------------
__device__ __forceinline__ uint32_t pack_bf16(float e0, float e1) {
  uint32_t d;
  asm("cvt.rn.bf16x2.f32 %0, %1, %2;" : "=r"(d) : "f"(e1), "f"(e0));
  return d;
}
__device__ __forceinline__ void split_pair(float a0, float a1, uint32_t& hp, uint32_t& lp) {
  hp = pack_bf16(a0, a1);
  float r0 = a0 - __uint_as_float(hp << 16);
  float r1 = a1 - __uint_as_float(hp & 0xffff0000u);
  lp = pack_bf16(r0, r1);
}
__device__ __forceinline__ void mma_bf16(float* c, const uint32_t* a, const uint32_t* b) {
  asm volatile(
      "mma.sync.aligned.m16n8k16.row.col.f32.bf16.bf16.f32 "
      "{%0,%1,%2,%3}, {%4,%5,%6,%7}, {%8,%9}, {%0,%1,%2,%3};"
      : "+f"(c[0]), "+f"(c[1]), "+f"(c[2]), "+f"(c[3])
      : "r"(a[0]), "r"(a[1]), "r"(a[2]), "r"(a[3]), "r"(b[0]), "r"(b[1]));
}

// ================= fp32 SGEMM body (R4-exact arithmetic) ================
__device__ __forceinline__ void sgemm_body(
    char* sm, const float* A, const float* B, float* Cc,
    int K, int lda, int ldb, int ldc, int bm, int bn) {
  float (*As)[8][128] = reinterpret_cast<float(*)[8][128]>(sm);
  float (*Bs)[8][132] = reinterpret_cast<float(*)[8][132]>(sm + 8192);
  const int tid = threadIdx.x;
  const int tx = tid & 15, ty = tid >> 4;
  const int arow = tid >> 1, acol = (tid & 1) * 4;
  const int brow = tid >> 5, bcol = (tid & 31) * 4;

  const float* Aptr = A + (size_t)(bm + arow) * lda + acol;
  const float* Bptr = B + (size_t)brow * ldb + bn + bcol;

  float acc[8][8];
#pragma unroll
  for (int i = 0; i < 8; i++)
#pragma unroll
    for (int j = 0; j < 8; j++) acc[i][j] = 0.f;

  {
    float4 av = *reinterpret_cast<const float4*>(Aptr);
    float4 bv = *reinterpret_cast<const float4*>(Bptr);
    As[0][acol + 0][arow] = av.x;
    As[0][acol + 1][arow] = av.y;
    As[0][acol + 2][arow] = av.z;
    As[0][acol + 3][arow] = av.w;
    Bs[0][brow][bcol + 0] = bv.x;
    Bs[0][brow][bcol + 1] = bv.y;
    Bs[0][brow][bcol + 2] = bv.z;
    Bs[0][brow][bcol + 3] = bv.w;
  }
  __syncthreads();

  int buf = 0;
  for (int k0 = 0; k0 < K; k0 += 8) {
    float4 av, bv;
    const bool more = (k0 + 8 < K);
    if (more) {
      av = *reinterpret_cast<const float4*>(Aptr + k0 + 8);
      bv = *reinterpret_cast<const float4*>(Bptr + (size_t)(k0 + 8) * ldb);
    }
#pragma unroll
    for (int kk = 0; kk < 8; kk++) {
      float a[8], b[8];
#pragma unroll
      for (int i = 0; i < 8; i++) a[i] = As[buf][kk][ty * 8 + i];
#pragma unroll
      for (int j = 0; j < 8; j++) b[j] = Bs[buf][kk][tx * 8 + j];
#pragma unroll
      for (int i = 0; i < 8; i++)
#pragma unroll
        for (int j = 0; j < 8; j++) acc[i][j] += a[i] * b[j];
    }
    if (more) {
      int nb = buf ^ 1;
      As[nb][acol + 0][arow] = av.x;
      As[nb][acol + 1][arow] = av.y;
      As[nb][acol + 2][arow] = av.z;
      As[nb][acol + 3][arow] = av.w;
      Bs[nb][brow][bcol + 0] = bv.x;
      Bs[nb][brow][bcol + 1] = bv.y;
      Bs[nb][brow][bcol + 2] = bv.z;
      Bs[nb][brow][bcol + 3] = bv.w;
      __syncthreads();
      buf = nb;
    }
  }

#pragma unroll
  for (int i = 0; i < 8; i++) {
    float* crow = Cc + (size_t)(bm + ty * 8 + i) * ldc + bn + tx * 8;
    *reinterpret_cast<float4*>(crow) = make_float4(acc[i][0], acc[i][1], acc[i][2], acc[i][3]);
    *reinterpret_cast<float4*>(crow + 4) = make_float4(acc[i][4], acc[i][5], acc[i][6], acc[i][7]);
  }
}

// ================= proj64 body; optional fused chunk-mean A ============
__device__ __forceinline__ float4 ld_mean4(const float* p) {
  float4 a = *reinterpret_cast<const float4*>(p);
  float4 b = *reinterpret_cast<const float4*>(p + D_DIM);
  float4 c = *reinterpret_cast<const float4*>(p + 2 * D_DIM);
  float4 d = *reinterpret_cast<const float4*>(p + 3 * D_DIM);
  return make_float4(0.25f * (((a.x + b.x) + c.x) + d.x),
                     0.25f * (((a.y + b.y) + c.y) + d.y),
                     0.25f * (((a.z + b.z) + c.z) + d.z),
                     0.25f * (((a.w + b.w) + c.w) + d.w));
}

__device__ __forceinline__ void proj64_body(
    char* sm, const float* A, const float* B, float* Cc, int bm, bool mean4) {
  float (*As)[128] = reinterpret_cast<float(*)[128]>(sm);
  float (*Bs)[68] = reinterpret_cast<float(*)[68]>(sm + 4096);
  const int tid = threadIdx.x;
  const int tx = tid & 15, ty = tid >> 4;
  const int arow = tid >> 1, acol = (tid & 1) * 4;
  const int brow = tid >> 4, bcol = (tid & 15) * 4;
  const bool bload = (tid < 128);

  const float* Aptr = mean4 ? (A + (size_t)(4 * (bm + arow)) * D_DIM + acol)
                            : (A + (size_t)(bm + arow) * D_DIM + acol);
  const float* Bptr = B + (size_t)brow * C_DIM + bcol;

  float acc[8][4];
#pragma unroll
  for (int i = 0; i < 8; i++)
#pragma unroll
    for (int j = 0; j < 4; j++) acc[i][j] = 0.f;

  float4 av = mean4 ? ld_mean4(Aptr) : *reinterpret_cast<const float4*>(Aptr);
  float4 bv = bload ? *reinterpret_cast<const float4*>(Bptr) : make_float4(0, 0, 0, 0);

  for (int k0 = 0; k0 < D_DIM; k0 += 8) {
    As[acol + 0][arow] = av.x;
    As[acol + 1][arow] = av.y;
    As[acol + 2][arow] = av.z;
    As[acol + 3][arow] = av.w;
    if (bload) {
      Bs[brow][bcol + 0] = bv.x;
      Bs[brow][bcol + 1] = bv.y;
      Bs[brow][bcol + 2] = bv.z;
      Bs[brow][bcol + 3] = bv.w;
    }
    __syncthreads();

    if (k0 + 8 < D_DIM) {
      av = mean4 ? ld_mean4(Aptr + k0 + 8) : *reinterpret_cast<const float4*>(Aptr + k0 + 8);
      if (bload) bv = *reinterpret_cast<const float4*>(Bptr + (size_t)(k0 + 8) * C_DIM);
    }

#pragma unroll
    for (int kk = 0; kk < 8; kk++) {
      float a[8], b[4];
#pragma unroll
      for (int i = 0; i < 8; i++) a[i] = As[kk][ty * 8 + i];
#pragma unroll
      for (int j = 0; j < 4; j++) b[j] = Bs[kk][tx * 4 + j];
#pragma unroll
      for (int i = 0; i < 8; i++)
#pragma unroll
        for (int j = 0; j < 4; j++) acc[i][j] += a[i] * b[j];
    }
    __syncthreads();
  }

#pragma unroll
  for (int i = 0; i < 8; i++) {
    float* crow = Cc + (size_t)(bm + ty * 8 + i) * C_DIM + tx * 4;
    *reinterpret_cast<float4*>(crow) = make_float4(acc[i][0], acc[i][1], acc[i][2], acc[i][3]);
  }
}

// ================= hw body =============================================
__device__ __forceinline__ void hw_body(const float* x, const float* w_w, int blk) {
  int warp_g = blk * 8 + (threadIdx.x >> 5);
  int lane = threadIdx.x & 31;
  const float4* wr = reinterpret_cast<const float4*>(w_w);
  for (int row = warp_g; row < S_LEN; row += 256) {
    const float4* xr = reinterpret_cast<const float4*>(x + (size_t)row * D_DIM);
    float d0 = 0.f, d1 = 0.f, d2 = 0.f, d3 = 0.f;
    for (int i = lane; i < D_DIM / 4; i += 32) {
      float4 xv = xr[i];
      float4 w0 = wr[i * 4 + 0];
      float4 w1 = wr[i * 4 + 1];
      float4 w2 = wr[i * 4 + 2];
      float4 w3 = wr[i * 4 + 3];
      d0 += xv.x * w0.x + xv.y * w1.x + xv.z * w2.x + xv.w * w3.x;
      d1 += xv.x * w0.y + xv.y * w1.y + xv.z * w2.y + xv.w * w3.y;
      d2 += xv.x * w0.z + xv.y * w1.z + xv.z * w2.z + xv.w * w3.z;
      d3 += xv.x * w0.w + xv.y * w1.w + xv.z * w2.w + xv.w * w3.w;
    }
#pragma unroll
    for (int off = 16; off > 0; off >>= 1) {
      d0 += __shfl_down_sync(0xffffffffu, d0, off);
      d1 += __shfl_down_sync(0xffffffffu, d1, off);
      d2 += __shfl_down_sync(0xffffffffu, d2, off);
      d3 += __shfl_down_sync(0xffffffffu, d3, off);
    }
    if (lane == 0) {
      g_hw[row * 4 + 0] = d0;
      g_hw[row * 4 + 1] = d1;
      g_hw[row * 4 + 2] = d2;
      g_hw[row * 4 + 3] = d3;
    }
  }
}

// ================= superA ==============================================
struct SuperAArgs {
  const float* x;
  const float* w_dq;
  const float* w_kva;
  const float* w_kvb;
  const float* w_za;
  const float* w_zb;
  const float* w_k;
  const float* w_w;
  float* cq;
  float* ca;
  float* cb;
  float* za;
  float* zb;
  float* kp;
};

__global__ __launch_bounds__(256, 2) void superA_kernel(SuperAArgs a) {
  __shared__ __align__(16) char sm[16640];
  int id = blockIdx.x;
  if (id < 128) {
    sgemm_body(sm, a.x, a.w_dq, a.cq, D_DIM, D_DIM, DC_N, DC_N,
               (id >> 2) * 128, (id & 3) * 128);
  } else if (id < 288) {
    int pid = id - 128;
    int mat = pid >> 5, by = pid & 31;
    int bm = by * 128;
    if (mat == 4) {
      if (bm >= NC_CH) return;
      proj64_body(sm, a.x, a.w_k, a.kp, bm, true);
    } else {
      const float* B = (mat == 0) ? a.w_kva : (mat == 1) ? a.w_kvb : (mat == 2) ? a.w_za : a.w_zb;
      float* C = (mat == 0) ? a.ca : (mat == 1) ? a.cb : (mat == 2) ? a.za : a.zb;
      proj64_body(sm, a.x, B, C, bm, false);
    }
  } else {
    hw_body(a.x, a.w_w, id - 288);
  }
}

// ================= tensor GEMM body (R9 bf16 3-term) ===================
__device__ __forceinline__ void tgemm_body(
    char* sm, const float* A, const float* B, float* Cc,
    int K, int lda, int ldb, int ldc, int bm, int bn) {
  uint32_t* Ah = reinterpret_cast<uint32_t*>(sm);
  uint32_t* Al = reinterpret_cast<uint32_t*>(sm + 12288);
  uint32_t* Bh = reinterpret_cast<uint32_t*>(sm + 24576);
  uint32_t* Bl = reinterpret_cast<uint32_t*>(sm + 33280);
#define AH(b, r, p) Ah[(b) * 1536 + (r) * 12 + (p)]
#define AL(b, r, p) Al[(b) * 1536 + (r) * 12 + (p)]
#define BH(b, r, c) Bh[(b) * 1088 + (r) * 136 + (c)]
#define BL(b, r, c) Bl[(b) * 1088 + (r) * 136 + (c)]

  const int tid = threadIdx.x;
  const int warp = tid >> 5, lane = tid & 31;
  const int wm = warp >> 2, wn = warp & 3;
  const int g = lane >> 2, t = lane & 3;

  const int arow = tid >> 1, akoff = (tid & 1) * 8;
  const int brp = tid >> 5, bcol = lane * 4;

  const float* Aptr = A + (size_t)(bm + arow) * lda + akoff;
  const float* Bptr0 = B + (size_t)(2 * brp) * ldb + bn + bcol;
  const float* Bptr1 = Bptr0 + ldb;

  float acc[4][4][4];
#pragma unroll
  for (int i = 0; i < 4; i++)
#pragma unroll
    for (int j = 0; j < 4; j++)
#pragma unroll
      for (int r = 0; r < 4; r++) acc[i][j][r] = 0.f;

  float4 av0 = *reinterpret_cast<const float4*>(Aptr);
  float4 av1 = *reinterpret_cast<const float4*>(Aptr + 4);
  float4 bv0 = *reinterpret_cast<const float4*>(Bptr0);
  float4 bv1 = *reinterpret_cast<const float4*>(Bptr1);
  {
    uint32_t h[4], l[4];
    split_pair(av0.x, av0.y, h[0], l[0]);
    split_pair(av0.z, av0.w, h[1], l[1]);
    split_pair(av1.x, av1.y, h[2], l[2]);
    split_pair(av1.z, av1.w, h[3], l[3]);
    int ac = akoff >> 1;
    *reinterpret_cast<uint4*>(&AH(0, arow, ac)) = make_uint4(h[0], h[1], h[2], h[3]);
    *reinterpret_cast<uint4*>(&AL(0, arow, ac)) = make_uint4(l[0], l[1], l[2], l[3]);
    uint32_t bh[4], bl[4];
    split_pair(bv0.x, bv1.x, bh[0], bl[0]);
    split_pair(bv0.y, bv1.y, bh[1], bl[1]);
    split_pair(bv0.z, bv1.z, bh[2], bl[2]);
    split_pair(bv0.w, bv1.w, bh[3], bl[3]);
    *reinterpret_cast<uint4*>(&BH(0, brp, bcol)) = make_uint4(bh[0], bh[1], bh[2], bh[3]);
    *reinterpret_cast<uint4*>(&BL(0, brp, bcol)) = make_uint4(bl[0], bl[1], bl[2], bl[3]);
  }
  __syncthreads();

  int buf = 0;
  for (int k0 = 0; k0 < K; k0 += 16) {
    const bool more = (k0 + 16 < K);
    if (more) {
      av0 = *reinterpret_cast<const float4*>(Aptr + k0 + 16);
      av1 = *reinterpret_cast<const float4*>(Aptr + k0 + 20);
      bv0 = *reinterpret_cast<const float4*>(Bptr0 + (size_t)(k0 + 16) * ldb);
      bv1 = *reinterpret_cast<const float4*>(Bptr1 + (size_t)(k0 + 16) * ldb);
    }

    {
      uint32_t bhf[4][2], blf[4][2];
#pragma unroll
      for (int ni = 0; ni < 4; ni++) {
        int colB = wn * 32 + ni * 8 + g;
        bhf[ni][0] = BH(buf, t, colB);
        bhf[ni][1] = BH(buf, t + 4, colB);
        blf[ni][0] = BL(buf, t, colB);
        blf[ni][1] = BL(buf, t + 4, colB);
      }
#pragma unroll
      for (int mi = 0; mi < 4; mi++) {
        int rowA = wm * 64 + mi * 16 + g;
        uint32_t ah[4], al[4];
        ah[0] = AH(buf, rowA, t);
        ah[1] = AH(buf, rowA + 8, t);
        ah[2] = AH(buf, rowA, t + 4);
        ah[3] = AH(buf, rowA + 8, t + 4);
        al[0] = AL(buf, rowA, t);
        al[1] = AL(buf, rowA + 8, t);
        al[2] = AL(buf, rowA, t + 4);
        al[3] = AL(buf, rowA + 8, t + 4);
#pragma unroll
        for (int ni = 0; ni < 4; ni++) mma_bf16(acc[mi][ni], ah, bhf[ni]);
#pragma unroll
        for (int ni = 0; ni < 4; ni++) mma_bf16(acc[mi][ni], ah, blf[ni]);
#pragma unroll
        for (int ni = 0; ni < 4; ni++) mma_bf16(acc[mi][ni], al, bhf[ni]);
      }
    }

    if (more) {
      int nb = buf ^ 1;
      uint32_t h[4], l[4];
      split_pair(av0.x, av0.y, h[0], l[0]);
      split_pair(av0.z, av0.w, h[1], l[1]);
      split_pair(av1.x, av1.y, h[2], l[2]);
      split_pair(av1.z, av1.w, h[3], l[3]);
      int ac = akoff >> 1;
      *reinterpret_cast<uint4*>(&AH(nb, arow, ac)) = make_uint4(h[0], h[1], h[2], h[3]);
      *reinterpret_cast<uint4*>(&AL(nb, arow, ac)) = make_uint4(l[0], l[1], l[2], l[3]);
      uint32_t bh[4], bl[4];
      split_pair(bv0.x, bv1.x, bh[0], bl[0]);
      split_pair(bv0.y, bv1.y, bh[1], bl[1]);
      split_pair(bv0.z, bv1.z, bh[2], bl[2]);
      split_pair(bv0.w, bv1.w, bh[3], bl[3]);
      *reinterpret_cast<uint4*>(&BH(nb, brp, bcol)) = make_uint4(bh[0], bh[1], bh[2], bh[3]);
      *reinterpret_cast<uint4*>(&BL(nb, brp, bcol)) = make_uint4(bl[0], bl[1], bl[2], bl[3]);
      __syncthreads();
      buf = nb;
    }
  }

#pragma unroll
  for (int mi = 0; mi < 4; mi++) {
    int row0 = bm + wm * 64 + mi * 16 + g;
#pragma unroll
    for (int ni = 0; ni < 4; ni++) {
      int col = bn + wn * 32 + ni * 8 + 2 * t;
      *reinterpret_cast<float2*>(Cc + (size_t)row0 * ldc + col) =
          make_float2(acc[mi][ni][0], acc[mi][ni][1]);
      *reinterpret_cast<float2*>(Cc + (size_t)(row0 + 8) * ldc + col) =
          make_float2(acc[mi][ni][2], acc[mi][ni][3]);
    }
  }
#undef AH
#undef AL
#undef BH
#undef BL
}

__global__ __launch_bounds__(256) void tgemm_kernel(
    const float* __restrict__ A, const float* __restrict__ B,
    float* __restrict__ Cc, int K, int lda, int ldb, int ldc,
    long sA, long sB, long sC) {
  __shared__ __align__(16) char sm[41984];
  tgemm_body(sm, A + (long)blockIdx.z * sA, B + (long)blockIdx.z * sB,
             Cc + (long)blockIdx.z * sC, K, lda, ldb, ldc,
             blockIdx.y * 128, blockIdx.x * 128);
}

// ================= superC: q_i fp32 GEMM || w_uq tensor GEMM ============
__global__ __launch_bounds__(256) void superC_kernel(
    const float* __restrict__ cq, const float* __restrict__ w_iuq,
    const float* __restrict__ w_uq, float* __restrict__ qi, float* __restrict__ qf) {
  __shared__ __align__(16) char sm[41984];
  int id = blockIdx.x;
  if (id < 64) {
    sgemm_body(sm, cq, w_iuq, qi, DC_N, DC_N, NHI_N * CI_N, NHI_N * CI_N,
               (id >> 1) * 128, (id & 1) * 128);
  } else {
    int tid2 = id - 64;
    tgemm_body(sm, cq, w_uq, qf, DC_N, DC_N, NH_N * C_DIM, NH_N * C_DIM,
               (tid2 >> 3) * 128, (tid2 & 7) * 128);
  }
}

// ------------- compression softmax + LayerNorm --------------------------
__global__ void compress_kernel(const float* __restrict__ b_a,
                                const float* __restrict__ b_b,
                                const float* __restrict__ kvn_w,
                                const float* __restrict__ kvn_b) {
  int nc = blockIdx.x;
  int c = threadIdx.x;  // 64
  float lg[8], val[8];
#pragma unroll
  for (int m = 0; m < 4; m++) {
    int cur = (nc * 4 + m) * 64 + c;
    lg[4 + m] = g_za[cur] + b_a[m * 64 + c];
    val[4 + m] = g_ca[cur];
    if (nc > 0) {
      int prev = ((nc - 1) * 4 + m) * 64 + c;
      lg[m] = g_zb[prev] + b_b[m * 64 + c];
      val[m] = g_cb[prev];
    } else {
      lg[m] = -1e30f + b_b[m * 64 + c];
      val[m] = 0.f;
    }
  }
  float mx = lg[0];
#pragma unroll
  for (int i = 1; i < 8; i++) mx = fmaxf(mx, lg[i]);
  float se = 0.f, comp = 0.f;
#pragma unroll
  for (int i = 0; i < 8; i++) {
    float e = expf(lg[i] - mx);
    se += e;
    comp += e * val[i];
  }
  comp /= se;

  __shared__ float red[64];
  red[c] = comp;
  __syncthreads();
  for (int off = 32; off > 0; off >>= 1) {
    if (c < off) red[c] += red[c + off];
    __syncthreads();
  }
  float mu = red[0] * (1.f / 64.f);
  __syncthreads();
  float dv = comp - mu;
  red[c] = dv * dv;
  __syncthreads();
  for (int off = 32; off > 0; off >>= 1) {
    if (c < off) red[c] += red[c + off];
    __syncthreads();
  }
  float var = red[0] * (1.f / 64.f);
  g_kc[nc * 64 + c] = dv * rsqrtf(var + 1e-6f) * kvn_w[c] + kvn_b[c];
}

// ------------- per-(s,h) LayerNorm then RoPE ----------------------------
__global__ void qln_rope_kernel(const float* __restrict__ qn_w,
                                const float* __restrict__ qn_b) {
  int s = blockIdx.x;
  int c = threadIdx.x;  // 64
  int h = threadIdx.y;  // 16
  float v = g_qf[(size_t)s * 1024 + h * 64 + c];
  __shared__ float red[16][64];
  __shared__ float lnb[16][65];
  red[h][c] = v;
  __syncthreads();
  for (int off = 32; off > 0; off >>= 1) {
    if (c < off) red[h][c] += red[h][c + off];
    __syncthreads();
  }
  float mu = red[h][0] * (1.f / 64.f);
  __syncthreads();
  float dv = v - mu;
  red[h][c] = dv * dv;
  __syncthreads();
  for (int off = 32; off > 0; off >>= 1) {
    if (c < off) red[h][c] += red[h][c + off];
    __syncthreads();
  }
  float var = red[h][0] * (1.f / 64.f);
  float ln = dv * rsqrtf(var + 1e-6f) * qn_w[c] + qn_b[c];
  lnb[h][c] = ln;
  __syncthreads();
  float outv;
  if (c < 32) {
    outv = ln;
  } else {
    int j = (c - 32) >> 1;
    float inv = exp2f(-(float)j * 0.830482023722f);  // 10000^(-j/16)
    float ang = (float)s * inv;
    float cs = cosf(ang), sn = sinf(ang);
    float x0 = lnb[h][32 + 2 * j], x1 = lnb[h][32 + 2 * j + 1];
    outv = ((c & 1) == 0) ? (x0 * cs - x1 * sn) : (x0 * sn + x1 * cs);
  }
  g_qf[(size_t)s * 1024 + h * 64 + c] = outv;
}

// ------------- indexer scores (R12 verbatim: 256 thr, 4 chunks/thr) -----
__global__ void iscore_kernel() {
  int s = blockIdx.x;
  __shared__ float qs[256];
  __shared__ float ws[4];
  int tid = threadIdx.x;  // 256
  qs[tid] = g_qi[(size_t)s * 256 + tid];
  if (tid < 4) ws[tid] = g_hw[s * 4 + tid];
  __syncthreads();
  const float4* qs4 = reinterpret_cast<const float4*>(qs);
  for (int k = tid; k < NC_CH; k += 256) {
    const float4* kr = reinterpret_cast<const float4*>(g_kp + k * 64);
    float d0 = 0.f, d1 = 0.f, d2 = 0.f, d3 = 0.f;
#pragma unroll
    for (int c4 = 0; c4 < 16; c4++) {
      float4 kv = kr[c4];
      float4 q0 = qs4[c4];
      float4 q1 = qs4[16 + c4];
      float4 q2 = qs4[32 + c4];
      float4 q3 = qs4[48 + c4];
      d0 += q0.x * kv.x + q0.y * kv.y + q0.z * kv.z + q0.w * kv.w;
      d1 += q1.x * kv.x + q1.y * kv.y + q1.z * kv.z + q1.w * kv.w;
      d2 += q2.x * kv.x + q2.y * kv.y + q2.z * kv.z + q2.w * kv.w;
      d3 += q3.x * kv.x + q3.y * kv.y + q3.z * kv.z + q3.w * kv.w;
    }
    float sc = fmaxf(d0, 0.f) * ws[0] + fmaxf(d1, 0.f) * ws[1] +
               fmaxf(d2, 0.f) * ws[2] + fmaxf(d3, 0.f) * ws[3];
    g_is[(size_t)s * NC_CH + k] = (k < s) ? sc : NEG_INF;
  }
}

// ------------- exact top-512: PACKED u64 bitonic sort -------------------
// key = (monotonic(value) << 32) | (1023 - index).
// keyA > keyB  <=>  (va > vb) || (va == vb && ia < ib)  — identical total
// order to the R12 comparator, so g_ti is bit-identical. One u64 compare +
// swap instead of float+int pairs.
__global__ __launch_bounds__(512) void topk_kernel() {
  int s = blockIdx.x, tid = threadIdx.x;  // 512
  __shared__ unsigned long long kv[1024];
#pragma unroll
  for (int i = 0; i < 2; i++) {
    int k = tid + 512 * i;
    uint32_t b = __float_as_uint(g_is[(size_t)s * 1024 + k]);
    uint32_t m = (b & 0x80000000u) ? ~b : (b | 0x80000000u);
    kv[k] = ((unsigned long long)m << 32) | (unsigned)(1023 - k);
  }
  __syncthreads();
  for (int k = 2; k <= 1024; k <<= 1) {
    for (int j = k >> 1; j > 0; j >>= 1) {
#pragma unroll
      for (int w = 0; w < 2; w++) {
        int t = tid + 512 * w;
        int p = t ^ j;
        if (p > t) {
          unsigned long long a = kv[t], b2 = kv[p];
          bool before = (a > b2);
          bool dir = ((t & k) == 0);
          if (before != dir) {
            kv[t] = b2;
            kv[p] = a;
          }
        }
      }
      __syncthreads();
    }
  }
  g_ti[(size_t)s * 512 + tid] = 1023 - (int)(unsigned)(kv[tid] & 0xffffffffu);
}

// ------------- gathered sparse attention (R12 verbatim, 256 thr) --------
__global__ __launch_bounds__(256) void attn_kernel(const float* __restrict__ sink) {
  const int s = blockIdx.x, tid = threadIdx.x;  // 256
  __shared__ float qs[1024];
  __shared__ float Ks[128][68];
  __shared__ float ew[16][128];
  __shared__ float denom[16];

#pragma unroll
  for (int i = 0; i < 4; i++) qs[tid + 256 * i] = g_qf[(size_t)s * 1024 + tid + 256 * i];
  if (tid < 16) denom[tid] = __expf(sink[tid]);
  __syncthreads();

  const int c = tid & 63, g = tid >> 6;
  float acc0 = 0.f, acc1 = 0.f, acc2 = 0.f, acc3 = 0.f;
  const float4* qs4 = reinterpret_cast<const float4*>(qs);
  const int* trow = g_ti + (size_t)s * 512;

  for (int qtr = 0; qtr < 4; qtr++) {
    if (qtr) __syncthreads();

    {
      int j = tid >> 1, p = tid & 1;
      int ck = trow[qtr * 128 + j];
      const float4* src = reinterpret_cast<const float4*>(g_kc + ck * 64);
      float4* dst = reinterpret_cast<float4*>(&Ks[j][0]);
#pragma unroll
      for (int q = 0; q < 8; q++) dst[p + 2 * q] = src[p + 2 * q];
    }
    __syncthreads();

    {
      int kk = tid >> 1, hh = (tid & 1) * 8;
      int ck = trow[qtr * 128 + kk];
      bool valid = (s < ck * 4);
      const float4* kr = reinterpret_cast<const float4*>(&Ks[kk][0]);
      float d[8];
#pragma unroll
      for (int h = 0; h < 8; h++) d[h] = 0.f;
#pragma unroll
      for (int c4 = 0; c4 < 16; c4++) {
        float4 kv = kr[c4];
#pragma unroll
        for (int h = 0; h < 8; h++) {
          float4 qv = qs4[(hh + h) * 16 + c4];
          d[h] += qv.x * kv.x + qv.y * kv.y + qv.z * kv.z + qv.w * kv.w;
        }
      }
#pragma unroll
      for (int h = 0; h < 8; h++) ew[hh + h][kk] = valid ? __expf(d[h] * 0.125f) : 0.f;
    }
    __syncthreads();

    {
      int h = tid >> 4, seg = tid & 15;
      float4 v0 = *reinterpret_cast<const float4*>(&ew[h][seg * 8]);
      float4 v1 = *reinterpret_cast<const float4*>(&ew[h][seg * 8 + 4]);
      float p = v0.x + v0.y + v0.z + v0.w + v1.x + v1.y + v1.z + v1.w;
#pragma unroll
      for (int off = 8; off > 0; off >>= 1) p += __shfl_down_sync(0xffffffffu, p, off);
      if (seg == 0) denom[h] += p;
    }

    for (int k4 = 0; k4 < 128; k4 += 4) {
      float4 e0 = *reinterpret_cast<const float4*>(&ew[g][k4]);
      float4 e1 = *reinterpret_cast<const float4*>(&ew[g + 4][k4]);
      float4 e2 = *reinterpret_cast<const float4*>(&ew[g + 8][k4]);
      float4 e3 = *reinterpret_cast<const float4*>(&ew[g + 12][k4]);
      float kv0 = Ks[k4 + 0][c];
      float kv1 = Ks[k4 + 1][c];
      float kv2 = Ks[k4 + 2][c];
      float kv3 = Ks[k4 + 3][c];
      acc0 += e0.x * kv0 + e0.y * kv1 + e0.z * kv2 + e0.w * kv3;
      acc1 += e1.x * kv0 + e1.y * kv1 + e1.z * kv2 + e1.w * kv3;
      acc2 += e2.x * kv0 + e2.y * kv1 + e2.z * kv2 + e2.w * kv3;
      acc3 += e3.x * kv0 + e3.y * kv1 + e3.z * kv2 + e3.w * kv3;
    }
  }
  __syncthreads();

  g_ao[(size_t)s * 1024 + (g) * 64 + c] = acc0 / denom[g];
  g_ao[(size_t)s * 1024 + (g + 4) * 64 + c] = acc1 / denom[g + 4];
  g_ao[(size_t)s * 1024 + (g + 8) * 64 + c] = acc2 / denom[g + 8];
  g_ao[(size_t)s * 1024 + (g + 12) * 64 + c] = acc3 / denom[g + 12];
}

// ---------------------------- launcher ----------------------------------
extern "C" void kernel_launch(void* const* d_in, const int* in_sizes, int n_in,
                              void* d_out, int out_size) {
  (void)in_sizes; (void)n_in; (void)out_size;
  const float* x      = (const float*)d_in[0];
  const float* w_kva  = (const float*)d_in[1];
  const float* w_kvb  = (const float*)d_in[2];
  const float* w_za   = (const float*)d_in[3];
  const float* w_zb   = (const float*)d_in[4];
  const float* b_a    = (const float*)d_in[5];
  const float* b_b    = (const float*)d_in[6];
  const float* w_dq   = (const float*)d_in[7];
  const float* w_iuq  = (const float*)d_in[8];
  const float* w_w    = (const float*)d_in[9];
  const float* w_k    = (const float*)d_in[10];
  const float* w_uq   = (const float*)d_in[11];
  const float* o_down = (const float*)d_in[12];
  const float* o_up   = (const float*)d_in[13];
  const float* kvn_w  = (const float*)d_in[14];
  const float* kvn_b  = (const float*)d_in[15];
  const float* qn_w   = (const float*)d_in[16];
  const float* qn_b   = (const float*)d_in[17];
  const float* sink   = (const float*)d_in[18];
  float* out = (float*)d_out;

  void *p_ca, *p_cb, *p_za, *p_zb, *p_cq, *p_qi, *p_kp, *p_qf, *p_ao, *p_gb;
  cudaGetSymbolAddress(&p_ca, g_ca);
  cudaGetSymbolAddress(&p_cb, g_cb);
  cudaGetSymbolAddress(&p_za, g_za);
  cudaGetSymbolAddress(&p_zb, g_zb);
  cudaGetSymbolAddress(&p_cq, g_cq);
  cudaGetSymbolAddress(&p_qi, g_qi);
  cudaGetSymbolAddress(&p_kp, g_kp);
  cudaGetSymbolAddress(&p_qf, g_qf);
  cudaGetSymbolAddress(&p_ao, g_ao);
  cudaGetSymbolAddress(&p_gb, g_gb);

  // superA: c_q GEMM (128) || projections incl. fused chunk-mean (160) || hw (32)
  SuperAArgs sa;
  sa.x = x;
  sa.w_dq = w_dq;
  sa.w_kva = w_kva;
  sa.w_kvb = w_kvb;
  sa.w_za = w_za;
  sa.w_zb = w_zb;
  sa.w_k = w_k;
  sa.w_w = w_w;
  sa.cq = (float*)p_cq;
  sa.ca = (float*)p_ca;
  sa.cb = (float*)p_cb;
  sa.za = (float*)p_za;
  sa.zb = (float*)p_zb;
  sa.kp = (float*)p_kp;
  superA_kernel<<<320, 256>>>(sa);

  // chunk compression + LN(kc)
  compress_kernel<<<NC_CH, 64>>>(b_a, b_b, kvn_w, kvn_b);

  // superC: q_i fp32 GEMM (64) || w_uq tensor GEMM (256)
  superC_kernel<<<320, 256>>>((const float*)p_cq, w_iuq, w_uq, (float*)p_qi, (float*)p_qf);

  // LN+rope on q; indexer scoring; exact top-k (packed u64 sort)
  qln_rope_kernel<<<S_LEN, dim3(64, 16)>>>(qn_w, qn_b);
  iscore_kernel<<<S_LEN, 256>>>();
  topk_kernel<<<S_LEN, 512>>>();

  // sparse attention over top-k compressed chunks
  attn_kernel<<<S_LEN, 256>>>(sink);

  // grouped o_down: batched tensor GEMM
  tgemm_kernel<<<dim3(DG_N / 128, S_LEN / 128, NG_N), 256>>>(
      (const float*)p_ao, o_down, (float*)p_gb,
      256, NH_N * C_DIM, DG_N, NG_N * DG_N,
      /*sA=*/256, /*sB=*/(long)256 * DG_N, /*sC=*/DG_N);

  // o_up (tensor)
  tgemm_kernel<<<dim3(D_DIM / 128, S_LEN / 128, 1), 256>>>(
      (const float*)p_gb, o_up, out,
      NG_N * DG_N, NG_N * DG_N, D_DIM, D_DIM, 0, 0, 0);
}

// round 16
// speedup vs baseline: 1.6003x; 1.0056x over previous
#include <cuda_runtime.h>
#include <cuda_bf16.h>
#include <cstdint>
#include <cstddef>

// ---------------- problem constants ----------------
#define S_LEN   4096
#define D_DIM   2048
#define C_DIM   64
#define NC_CH   1024
#define TOPK_N  512
#define NH_N    16
#define DC_N    512
#define NHI_N   4
#define CI_N    64
#define NG_N    4
#define DG_N    512

#define NEG_INF (__int_as_float(0xff800000))

// ---------------- scratch ----------------
__device__ float g_cz[S_LEN * 256];     // fused [c_a | c_b | z_a | z_b] per row
__device__ float g_wcz[D_DIM * 256];    // fused weights [w_kva|w_kvb|w_za|w_zb]
__device__ float g_kc[NC_CH * C_DIM];
__device__ float g_cq[S_LEN * DC_N];
__device__ float g_qi[S_LEN * NHI_N * CI_N];
__device__ float g_hw[S_LEN * NHI_N];
__device__ float g_kp[NC_CH * CI_N];
__device__ float g_qf[S_LEN * NH_N * C_DIM];
__device__ float g_is[(size_t)S_LEN * NC_CH];
__device__ int   g_ti[S_LEN * TOPK_N];
__device__ float g_ao[S_LEN * NH_N * C_DIM];
__device__ float g_gb[(size_t)S_LEN * NG_N * DG_N];

// ---------------- bf16 helpers ----------------
__device__ __forceinline__ uint32_t pack_bf16(float e0, float e1) {
  uint32_t d;
  asm("cvt.rn.bf16x2.f32 %0, %1, %2;" : "=r"(d) : "f"(e1), "f"(e0));
  return d;
}
__device__ __forceinline__ void split_pair(float a0, float a1, uint32_t& hp, uint32_t& lp) {
  hp = pack_bf16(a0, a1);
  float r0 = a0 - __uint_as_float(hp << 16);
  float r1 = a1 - __uint_as_float(hp & 0xffff0000u);
  lp = pack_bf16(r0, r1);
}
__device__ __forceinline__ void mma_bf16(float* c, const uint32_t* a, const uint32_t* b) {
  asm volatile(
      "mma.sync.aligned.m16n8k16.row.col.f32.bf16.bf16.f32 "
      "{%0,%1,%2,%3}, {%4,%5,%6,%7}, {%8,%9}, {%0,%1,%2,%3};"
      : "+f"(c[0]), "+f"(c[1]), "+f"(c[2]), "+f"(c[3])
      : "r"(a[0]), "r"(a[1]), "r"(a[2]), "r"(a[3]), "r"(b[0]), "r"(b[1]));
}

// ================= fp32 SGEMM body (R4-exact arithmetic) ================
__device__ __forceinline__ void sgemm_body(
    char* sm, const float* A, const float* B, float* Cc,
    int K, int lda, int ldb, int ldc, int bm, int bn) {
  float (*As)[8][128] = reinterpret_cast<float(*)[8][128]>(sm);
  float (*Bs)[8][132] = reinterpret_cast<float(*)[8][132]>(sm + 8192);
  const int tid = threadIdx.x;
  const int tx = tid & 15, ty = tid >> 4;
  const int arow = tid >> 1, acol = (tid & 1) * 4;
  const int brow = tid >> 5, bcol = (tid & 31) * 4;

  const float* Aptr = A + (size_t)(bm + arow) * lda + acol;
  const float* Bptr = B + (size_t)brow * ldb + bn + bcol;

  float acc[8][8];
#pragma unroll
  for (int i = 0; i < 8; i++)
#pragma unroll
    for (int j = 0; j < 8; j++) acc[i][j] = 0.f;

  {
    float4 av = *reinterpret_cast<const float4*>(Aptr);
    float4 bv = *reinterpret_cast<const float4*>(Bptr);
    As[0][acol + 0][arow] = av.x;
    As[0][acol + 1][arow] = av.y;
    As[0][acol + 2][arow] = av.z;
    As[0][acol + 3][arow] = av.w;
    Bs[0][brow][bcol + 0] = bv.x;
    Bs[0][brow][bcol + 1] = bv.y;
    Bs[0][brow][bcol + 2] = bv.z;
    Bs[0][brow][bcol + 3] = bv.w;
  }
  __syncthreads();

  int buf = 0;
  for (int k0 = 0; k0 < K; k0 += 8) {
    float4 av, bv;
    const bool more = (k0 + 8 < K);
    if (more) {
      av = *reinterpret_cast<const float4*>(Aptr + k0 + 8);
      bv = *reinterpret_cast<const float4*>(Bptr + (size_t)(k0 + 8) * ldb);
    }
#pragma unroll
    for (int kk = 0; kk < 8; kk++) {
      float a[8], b[8];
#pragma unroll
      for (int i = 0; i < 8; i++) a[i] = As[buf][kk][ty * 8 + i];
#pragma unroll
      for (int j = 0; j < 8; j++) b[j] = Bs[buf][kk][tx * 8 + j];
#pragma unroll
      for (int i = 0; i < 8; i++)
#pragma unroll
        for (int j = 0; j < 8; j++) acc[i][j] += a[i] * b[j];
    }
    if (more) {
      int nb = buf ^ 1;
      As[nb][acol + 0][arow] = av.x;
      As[nb][acol + 1][arow] = av.y;
      As[nb][acol + 2][arow] = av.z;
      As[nb][acol + 3][arow] = av.w;
      Bs[nb][brow][bcol + 0] = bv.x;
      Bs[nb][brow][bcol + 1] = bv.y;
      Bs[nb][brow][bcol + 2] = bv.z;
      Bs[nb][brow][bcol + 3] = bv.w;
      __syncthreads();
      buf = nb;
    }
  }

#pragma unroll
  for (int i = 0; i < 8; i++) {
    float* crow = Cc + (size_t)(bm + ty * 8 + i) * ldc + bn + tx * 8;
    *reinterpret_cast<float4*>(crow) = make_float4(acc[i][0], acc[i][1], acc[i][2], acc[i][3]);
    *reinterpret_cast<float4*>(crow + 4) = make_float4(acc[i][4], acc[i][5], acc[i][6], acc[i][7]);
  }
}

// ================= proj64 body (fp32; used for k_proj w/ chunk-mean) ====
__device__ __forceinline__ float4 ld_mean4(const float* p) {
  float4 a = *reinterpret_cast<const float4*>(p);
  float4 b = *reinterpret_cast<const float4*>(p + D_DIM);
  float4 c = *reinterpret_cast<const float4*>(p + 2 * D_DIM);
  float4 d = *reinterpret_cast<const float4*>(p + 3 * D_DIM);
  return make_float4(0.25f * (((a.x + b.x) + c.x) + d.x),
                     0.25f * (((a.y + b.y) + c.y) + d.y),
                     0.25f * (((a.z + b.z) + c.z) + d.z),
                     0.25f * (((a.w + b.w) + c.w) + d.w));
}

__device__ __forceinline__ void proj64_body(
    char* sm, const float* A, const float* B, float* Cc, int bm, bool mean4) {
  float (*As)[128] = reinterpret_cast<float(*)[128]>(sm);
  float (*Bs)[68] = reinterpret_cast<float(*)[68]>(sm + 4096);
  const int tid = threadIdx.x;
  const int tx = tid & 15, ty = tid >> 4;
  const int arow = tid >> 1, acol = (tid & 1) * 4;
  const int brow = tid >> 4, bcol = (tid & 15) * 4;
  const bool bload = (tid < 128);

  const float* Aptr = mean4 ? (A + (size_t)(4 * (bm + arow)) * D_DIM + acol)
                            : (A + (size_t)(bm + arow) * D_DIM + acol);
  const float* Bptr = B + (size_t)brow * C_DIM + bcol;

  float acc[8][4];
#pragma unroll
  for (int i = 0; i < 8; i++)
#pragma unroll
    for (int j = 0; j < 4; j++) acc[i][j] = 0.f;

  float4 av = mean4 ? ld_mean4(Aptr) : *reinterpret_cast<const float4*>(Aptr);
  float4 bv = bload ? *reinterpret_cast<const float4*>(Bptr) : make_float4(0, 0, 0, 0);

  for (int k0 = 0; k0 < D_DIM; k0 += 8) {
    As[acol + 0][arow] = av.x;
    As[acol + 1][arow] = av.y;
    As[acol + 2][arow] = av.z;
    As[acol + 3][arow] = av.w;
    if (bload) {
      Bs[brow][bcol + 0] = bv.x;
      Bs[brow][bcol + 1] = bv.y;
      Bs[brow][bcol + 2] = bv.z;
      Bs[brow][bcol + 3] = bv.w;
    }
    __syncthreads();

    if (k0 + 8 < D_DIM) {
      av = mean4 ? ld_mean4(Aptr + k0 + 8) : *reinterpret_cast<const float4*>(Aptr + k0 + 8);
      if (bload) bv = *reinterpret_cast<const float4*>(Bptr + (size_t)(k0 + 8) * C_DIM);
    }

#pragma unroll
    for (int kk = 0; kk < 8; kk++) {
      float a[8], b[4];
#pragma unroll
      for (int i = 0; i < 8; i++) a[i] = As[kk][ty * 8 + i];
#pragma unroll
      for (int j = 0; j < 4; j++) b[j] = Bs[kk][tx * 4 + j];
#pragma unroll
      for (int i = 0; i < 8; i++)
#pragma unroll
        for (int j = 0; j < 4; j++) acc[i][j] += a[i] * b[j];
    }
    __syncthreads();
  }

#pragma unroll
  for (int i = 0; i < 8; i++) {
    float* crow = Cc + (size_t)(bm + ty * 8 + i) * C_DIM + tx * 4;
    *reinterpret_cast<float4*>(crow) = make_float4(acc[i][0], acc[i][1], acc[i][2], acc[i][3]);
  }
}

// ================= hw body =============================================
__device__ __forceinline__ void hw_body(const float* x, const float* w_w, int blk) {
  int warp_g = blk * 8 + (threadIdx.x >> 5);
  int lane = threadIdx.x & 31;
  const float4* wr = reinterpret_cast<const float4*>(w_w);
  for (int row = warp_g; row < S_LEN; row += 256) {
    const float4* xr = reinterpret_cast<const float4*>(x + (size_t)row * D_DIM);
    float d0 = 0.f, d1 = 0.f, d2 = 0.f, d3 = 0.f;
    for (int i = lane; i < D_DIM / 4; i += 32) {
      float4 xv = xr[i];
      float4 w0 = wr[i * 4 + 0];
      float4 w1 = wr[i * 4 + 1];
      float4 w2 = wr[i * 4 + 2];
      float4 w3 = wr[i * 4 + 3];
      d0 += xv.x * w0.x + xv.y * w1.x + xv.z * w2.x + xv.w * w3.x;
      d1 += xv.x * w0.y + xv.y * w1.y + xv.z * w2.y + xv.w * w3.y;
      d2 += xv.x * w0.z + xv.y * w1.z + xv.z * w2.z + xv.w * w3.z;
      d3 += xv.x * w0.w + xv.y * w1.w + xv.z * w2.w + xv.w * w3.w;
    }
#pragma unroll
    for (int off = 16; off > 0; off >>= 1) {
      d0 += __shfl_down_sync(0xffffffffu, d0, off);
      d1 += __shfl_down_sync(0xffffffffu, d1, off);
      d2 += __shfl_down_sync(0xffffffffu, d2, off);
      d3 += __shfl_down_sync(0xffffffffu, d3, off);
    }
    if (lane == 0) {
      g_hw[row * 4 + 0] = d0;
      g_hw[row * 4 + 1] = d1;
      g_hw[row * 4 + 2] = d2;
      g_hw[row * 4 + 3] = d3;
    }
  }
}

// ================= tensor GEMM body (R9 bf16 3-term) ===================
__device__ __forceinline__ void tgemm_body(
    char* sm, const float* A, const float* B, float* Cc,
    int K, int lda, int ldb, int ldc, int bm, int bn) {
  uint32_t* Ah = reinterpret_cast<uint32_t*>(sm);
  uint32_t* Al = reinterpret_cast<uint32_t*>(sm + 12288);
  uint32_t* Bh = reinterpret_cast<uint32_t*>(sm + 24576);
  uint32_t* Bl = reinterpret_cast<uint32_t*>(sm + 33280);
#define AH(b, r, p) Ah[(b) * 1536 + (r) * 12 + (p)]
#define AL(b, r, p) Al[(b) * 1536 + (r) * 12 + (p)]
#define BH(b, r, c) Bh[(b) * 1088 + (r) * 136 + (c)]
#define BL(b, r, c) Bl[(b) * 1088 + (r) * 136 + (c)]

  const int tid = threadIdx.x;
  const int warp = tid >> 5, lane = tid & 31;
  const int wm = warp >> 2, wn = warp & 3;
  const int g = lane >> 2, t = lane & 3;

  const int arow = tid >> 1, akoff = (tid & 1) * 8;
  const int brp = tid >> 5, bcol = lane * 4;

  const float* Aptr = A + (size_t)(bm + arow) * lda + akoff;
  const float* Bptr0 = B + (size_t)(2 * brp) * ldb + bn + bcol;
  const float* Bptr1 = Bptr0 + ldb;

  float acc[4][4][4];
#pragma unroll
  for (int i = 0; i < 4; i++)
#pragma unroll
    for (int j = 0; j < 4; j++)
#pragma unroll
      for (int r = 0; r < 4; r++) acc[i][j][r] = 0.f;

  float4 av0 = *reinterpret_cast<const float4*>(Aptr);
  float4 av1 = *reinterpret_cast<const float4*>(Aptr + 4);
  float4 bv0 = *reinterpret_cast<const float4*>(Bptr0);
  float4 bv1 = *reinterpret_cast<const float4*>(Bptr1);
  {
    uint32_t h[4], l[4];
    split_pair(av0.x, av0.y, h[0], l[0]);
    split_pair(av0.z, av0.w, h[1], l[1]);
    split_pair(av1.x, av1.y, h[2], l[2]);
    split_pair(av1.z, av1.w, h[3], l[3]);
    int ac = akoff >> 1;
    *reinterpret_cast<uint4*>(&AH(0, arow, ac)) = make_uint4(h[0], h[1], h[2], h[3]);
    *reinterpret_cast<uint4*>(&AL(0, arow, ac)) = make_uint4(l[0], l[1], l[2], l[3]);
    uint32_t bh[4], bl[4];
    split_pair(bv0.x, bv1.x, bh[0], bl[0]);
    split_pair(bv0.y, bv1.y, bh[1], bl[1]);
    split_pair(bv0.z, bv1.z, bh[2], bl[2]);
    split_pair(bv0.w, bv1.w, bh[3], bl[3]);
    *reinterpret_cast<uint4*>(&BH(0, brp, bcol)) = make_uint4(bh[0], bh[1], bh[2], bh[3]);
    *reinterpret_cast<uint4*>(&BL(0, brp, bcol)) = make_uint4(bl[0], bl[1], bl[2], bl[3]);
  }
  __syncthreads();

  int buf = 0;
  for (int k0 = 0; k0 < K; k0 += 16) {
    const bool more = (k0 + 16 < K);
    if (more) {
      av0 = *reinterpret_cast<const float4*>(Aptr + k0 + 16);
      av1 = *reinterpret_cast<const float4*>(Aptr + k0 + 20);
      bv0 = *reinterpret_cast<const float4*>(Bptr0 + (size_t)(k0 + 16) * ldb);
      bv1 = *reinterpret_cast<const float4*>(Bptr1 + (size_t)(k0 + 16) * ldb);
    }

    {
      uint32_t bhf[4][2], blf[4][2];
#pragma unroll
      for (int ni = 0; ni < 4; ni++) {
        int colB = wn * 32 + ni * 8 + g;
        bhf[ni][0] = BH(buf, t, colB);
        bhf[ni][1] = BH(buf, t + 4, colB);
        blf[ni][0] = BL(buf, t, colB);
        blf[ni][1] = BL(buf, t + 4, colB);
      }
#pragma unroll
      for (int mi = 0; mi < 4; mi++) {
        int rowA = wm * 64 + mi * 16 + g;
        uint32_t ah[4], al[4];
        ah[0] = AH(buf, rowA, t);
        ah[1] = AH(buf, rowA + 8, t);
        ah[2] = AH(buf, rowA, t + 4);
        ah[3] = AH(buf, rowA + 8, t + 4);
        al[0] = AL(buf, rowA, t);
        al[1] = AL(buf, rowA + 8, t);
        al[2] = AL(buf, rowA, t + 4);
        al[3] = AL(buf, rowA + 8, t + 4);
#pragma unroll
        for (int ni = 0; ni < 4; ni++) mma_bf16(acc[mi][ni], ah, bhf[ni]);
#pragma unroll
        for (int ni = 0; ni < 4; ni++) mma_bf16(acc[mi][ni], ah, blf[ni]);
#pragma unroll
        for (int ni = 0; ni < 4; ni++) mma_bf16(acc[mi][ni], al, bhf[ni]);
      }
    }

    if (more) {
      int nb = buf ^ 1;
      uint32_t h[4], l[4];
      split_pair(av0.x, av0.y, h[0], l[0]);
      split_pair(av0.z, av0.w, h[1], l[1]);
      split_pair(av1.x, av1.y, h[2], l[2]);
      split_pair(av1.z, av1.w, h[3], l[3]);
      int ac = akoff >> 1;
      *reinterpret_cast<uint4*>(&AH(nb, arow, ac)) = make_uint4(h[0], h[1], h[2], h[3]);
      *reinterpret_cast<uint4*>(&AL(nb, arow, ac)) = make_uint4(l[0], l[1], l[2], l[3]);
      uint32_t bh[4], bl[4];
      split_pair(bv0.x, bv1.x, bh[0], bl[0]);
      split_pair(bv0.y, bv1.y, bh[1], bl[1]);
      split_pair(bv0.z, bv1.z, bh[2], bl[2]);
      split_pair(bv0.w, bv1.w, bh[3], bl[3]);
      *reinterpret_cast<uint4*>(&BH(nb, brp, bcol)) = make_uint4(bh[0], bh[1], bh[2], bh[3]);
      *reinterpret_cast<uint4*>(&BL(nb, brp, bcol)) = make_uint4(bl[0], bl[1], bl[2], bl[3]);
      __syncthreads();
      buf = nb;
    }
  }

#pragma unroll
  for (int mi = 0; mi < 4; mi++) {
    int row0 = bm + wm * 64 + mi * 16 + g;
#pragma unroll
    for (int ni = 0; ni < 4; ni++) {
      int col = bn + wn * 32 + ni * 8 + 2 * t;
      *reinterpret_cast<float2*>(Cc + (size_t)row0 * ldc + col) =
          make_float2(acc[mi][ni][0], acc[mi][ni][1]);
      *reinterpret_cast<float2*>(Cc + (size_t)(row0 + 8) * ldc + col) =
          make_float2(acc[mi][ni][2], acc[mi][ni][3]);
    }
  }
#undef AH
#undef AL
#undef BH
#undef BL
}

__global__ __launch_bounds__(256) void tgemm_kernel(
    const float* __restrict__ A, const float* __restrict__ B,
    float* __restrict__ Cc, int K, int lda, int ldb, int ldc,
    long sA, long sB, long sC) {
  __shared__ __align__(16) char sm[41984];
  tgemm_body(sm, A + (long)blockIdx.z * sA, B + (long)blockIdx.z * sB,
             Cc + (long)blockIdx.z * sC, K, lda, ldb, ldc,
             blockIdx.y * 128, blockIdx.x * 128);
}

// ======= weight concat: [w_kva|w_kvb|w_za|w_zb] -> g_wcz [2048][256] ====
__global__ void concatw_kernel(const float* __restrict__ wa, const float* __restrict__ wb,
                               const float* __restrict__ wza, const float* __restrict__ wzb) {
  int idx = blockIdx.x * 256 + threadIdx.x;
  if (idx >= D_DIM * C_DIM) return;
  int r = idx >> 6, c = idx & 63;
  g_wcz[r * 256 + c] = wa[idx];
  g_wcz[r * 256 + 64 + c] = wb[idx];
  g_wcz[r * 256 + 128 + c] = wza[idx];
  g_wcz[r * 256 + 192 + c] = wzb[idx];
}

// ================= superA ==============================================
// blocks: [0,128) c_q fp32 GEMM | [128,192) fused c/z tensor GEMM
//         [192,200) k_proj fp32 (chunk-mean) | [200,232) hw
struct SuperAArgs {
  const float* x;
  const float* w_dq;
  const float* w_k;
  const float* w_w;
  float* cq;
  float* cz;
  float* kp;
};

__global__ __launch_bounds__(256) void superA_kernel(SuperAArgs a) {
  __shared__ __align__(16) char sm[41984];
  int id = blockIdx.x;
  if (id < 128) {
    sgemm_body(sm, a.x, a.w_dq, a.cq, D_DIM, D_DIM, DC_N, DC_N,
               (id >> 2) * 128, (id & 3) * 128);
  } else if (id < 192) {
    int pid = id - 128;  // 64 blocks: 32 row tiles x 2 col tiles
    tgemm_body(sm, a.x, g_wcz, a.cz, D_DIM, D_DIM, 256, 256,
               (pid >> 1) * 128, (pid & 1) * 128);
  } else if (id < 200) {
    proj64_body(sm, a.x, a.w_k, a.kp, (id - 192) * 128, true);
  } else {
    hw_body(a.x, a.w_w, id - 200);
  }
}

// ================= superC: q_i fp32 GEMM || w_uq tensor GEMM ============
__global__ __launch_bounds__(256) void superC_kernel(
    const float* __restrict__ cq, const float* __restrict__ w_iuq,
    const float* __restrict__ w_uq, float* __restrict__ qi, float* __restrict__ qf) {
  __shared__ __align__(16) char sm[41984];
  int id = blockIdx.x;
  if (id < 64) {
    sgemm_body(sm, cq, w_iuq, qi, DC_N, DC_N, NHI_N * CI_N, NHI_N * CI_N,
               (id >> 1) * 128, (id & 1) * 128);
  } else {
    int tid2 = id - 64;
    tgemm_body(sm, cq, w_uq, qf, DC_N, DC_N, NH_N * C_DIM, NH_N * C_DIM,
               (tid2 >> 3) * 128, (tid2 & 7) * 128);
  }
}

// ------------- compression softmax + LayerNorm (reads fused g_cz) -------
__global__ void compress_kernel(const float* __restrict__ b_a,
                                const float* __restrict__ b_b,
                                const float* __restrict__ kvn_w,
                                const float* __restrict__ kvn_b) {
  int nc = blockIdx.x;
  int c = threadIdx.x;  // 64
  float lg[8], val[8];
#pragma unroll
  for (int m = 0; m < 4; m++) {
    int cur = (nc * 4 + m) * 256;
    lg[4 + m] = g_cz[cur + 128 + c] + b_a[m * 64 + c];   // z_a
    val[4 + m] = g_cz[cur + c];                          // c_a
    if (nc > 0) {
      int prev = ((nc - 1) * 4 + m) * 256;
      lg[m] = g_cz[prev + 192 + c] + b_b[m * 64 + c];    // z_b
      val[m] = g_cz[prev + 64 + c];                      // c_b
    } else {
      lg[m] = -1e30f + b_b[m * 64 + c];
      val[m] = 0.f;
    }
  }
  float mx = lg[0];
#pragma unroll
  for (int i = 1; i < 8; i++) mx = fmaxf(mx, lg[i]);
  float se = 0.f, comp = 0.f;
#pragma unroll
  for (int i = 0; i < 8; i++) {
    float e = expf(lg[i] - mx);
    se += e;
    comp += e * val[i];
  }
  comp /= se;

  __shared__ float red[64];
  red[c] = comp;
  __syncthreads();
  for (int off = 32; off > 0; off >>= 1) {
    if (c < off) red[c] += red[c + off];
    __syncthreads();
  }
  float mu = red[0] * (1.f / 64.f);
  __syncthreads();
  float dv = comp - mu;
  red[c] = dv * dv;
  __syncthreads();
  for (int off = 32; off > 0; off >>= 1) {
    if (c < off) red[c] += red[c + off];
    __syncthreads();
  }
  float var = red[0] * (1.f / 64.f);
  g_kc[nc * 64 + c] = dv * rsqrtf(var + 1e-6f) * kvn_w[c] + kvn_b[c];
}

// ------------- per-(s,h) LayerNorm then RoPE ----------------------------
__global__ void qln_rope_kernel(const float* __restrict__ qn_w,
                                const float* __restrict__ qn_b) {
  int s = blockIdx.x;
  int c = threadIdx.x;  // 64
  int h = threadIdx.y;  // 16
  float v = g_qf[(size_t)s * 1024 + h * 64 + c];
  __shared__ float red[16][64];
  __shared__ float lnb[16][65];
  red[h][c] = v;
  __syncthreads();
  for (int off = 32; off > 0; off >>= 1) {
    if (c < off) red[h][c] += red[h][c + off];
    __syncthreads();
  }
  float mu = red[h][0] * (1.f / 64.f);
  __syncthreads();
  float dv = v - mu;
  red[h][c] = dv * dv;
  __syncthreads();
  for (int off = 32; off > 0; off >>= 1) {
    if (c < off) red[h][c] += red[h][c + off];
    __syncthreads();
  }
  float var = red[h][0] * (1.f / 64.f);
  float ln = dv * rsqrtf(var + 1e-6f) * qn_w[c] + qn_b[c];
  lnb[h][c] = ln;
  __syncthreads();
  float outv;
  if (c < 32) {
    outv = ln;
  } else {
    int j = (c - 32) >> 1;
    float inv = exp2f(-(float)j * 0.830482023722f);  // 10000^(-j/16)
    float ang = (float)s * inv;
    float cs = cosf(ang), sn = sinf(ang);
    float x0 = lnb[h][32 + 2 * j], x1 = lnb[h][32 + 2 * j + 1];
    outv = ((c & 1) == 0) ? (x0 * cs - x1 * sn) : (x0 * sn + x1 * cs);
  }
  g_qf[(size_t)s * 1024 + h * 64 + c] = outv;
}

// ------------- indexer scores (R12 verbatim: 256 thr, 4 chunks/thr) -----
__global__ void iscore_kernel() {
  int s = blockIdx.x;
  __shared__ float qs[256];
  __shared__ float ws[4];
  int tid = threadIdx.x;  // 256
  qs[tid] = g_qi[(size_t)s * 256 + tid];
  if (tid < 4) ws[tid] = g_hw[s * 4 + tid];
  __syncthreads();
  const float4* qs4 = reinterpret_cast<const float4*>(qs);
  for (int k = tid; k < NC_CH; k += 256) {
    const float4* kr = reinterpret_cast<const float4*>(g_kp + k * 64);
    float d0 = 0.f, d1 = 0.f, d2 = 0.f, d3 = 0.f;
#pragma unroll
    for (int c4 = 0; c4 < 16; c4++) {
      float4 kv = kr[c4];
      float4 q0 = qs4[c4];
      float4 q1 = qs4[16 + c4];
      float4 q2 = qs4[32 + c4];
      float4 q3 = qs4[48 + c4];
      d0 += q0.x * kv.x + q0.y * kv.y + q0.z * kv.z + q0.w * kv.w;
      d1 += q1.x * kv.x + q1.y * kv.y + q1.z * kv.z + q1.w * kv.w;
      d2 += q2.x * kv.x + q2.y * kv.y + q2.z * kv.z + q2.w * kv.w;
      d3 += q3.x * kv.x + q3.y * kv.y + q3.z * kv.z + q3.w * kv.w;
    }
    float sc = fmaxf(d0, 0.f) * ws[0] + fmaxf(d1, 0.f) * ws[1] +
               fmaxf(d2, 0.f) * ws[2] + fmaxf(d3, 0.f) * ws[3];
    g_is[(size_t)s * NC_CH + k] = (k < s) ? sc : NEG_INF;
  }
}

// ------------- exact top-512: packed u64 half-sort + half-cleaner -------
// Stages k=2..512 leave half0 descending / half1 ascending => bitonic.
// One distance-512 compare-exchange (half-cleaner) puts the 512 largest
// keys (all distinct: index embedded) in the first half — the exact
// jax top-512 SET. Order within g_ti is irrelevant downstream (sum).
__global__ __launch_bounds__(512) void topk_kernel() {
  int s = blockIdx.x, tid = threadIdx.x;  // 512
  __shared__ unsigned long long kv[1024];
#pragma unroll
  for (int i = 0; i < 2; i++) {
    int k = tid + 512 * i;
    uint32_t b = __float_as_uint(g_is[(size_t)s * 1024 + k]);
    uint32_t m = (b & 0x80000000u) ? ~b : (b | 0x80000000u);
    kv[k] = ((unsigned long long)m << 32) | (unsigned)(1023 - k);
  }
  __syncthreads();
  for (int k = 2; k <= 512; k <<= 1) {
    for (int j = k >> 1; j > 0; j >>= 1) {
#pragma unroll
      for (int w = 0; w < 2; w++) {
        int t = tid + 512 * w;
        int p = t ^ j;
        if (p > t) {
          unsigned long long a = kv[t], b2 = kv[p];
          bool before = (a > b2);
          bool dir = ((t & k) == 0);
          if (before != dir) {
            kv[t] = b2;
            kv[p] = a;
          }
        }
      }
      __syncthreads();
    }
  }
  // half-cleaner: each thread owns pair (tid, tid+512); no cross-hazard
  unsigned long long a = kv[tid], b2 = kv[tid + 512];
  unsigned long long best = (a > b2) ? a : b2;
  g_ti[(size_t)s * 512 + tid] = 1023 - (int)(unsigned)(best & 0xffffffffu);
}

// ------------- gathered sparse attention (R12 verbatim, 256 thr) --------
__global__ __launch_bounds__(256) void attn_kernel(const float* __restrict__ sink) {
  const int s = blockIdx.x, tid = threadIdx.x;  // 256
  __shared__ float qs[1024];
  __shared__ float Ks[128][68];
  __shared__ float ew[16][128];
  __shared__ float denom[16];

#pragma unroll
  for (int i = 0; i < 4; i++) qs[tid + 256 * i] = g_qf[(size_t)s * 1024 + tid + 256 * i];
  if (tid < 16) denom[tid] = __expf(sink[tid]);
  __syncthreads();

  const int c = tid & 63, g = tid >> 6;
  float acc0 = 0.f, acc1 = 0.f, acc2 = 0.f, acc3 = 0.f;
  const float4* qs4 = reinterpret_cast<const float4*>(qs);
  const int* trow = g_ti + (size_t)s * 512;

  for (int qtr = 0; qtr < 4; qtr++) {
    if (qtr) __syncthreads();

    {
      int j = tid >> 1, p = tid & 1;
      int ck = trow[qtr * 128 + j];
      const float4* src = reinterpret_cast<const float4*>(g_kc + ck * 64);
      float4* dst = reinterpret_cast<float4*>(&Ks[j][0]);
#pragma unroll
      for (int q = 0; q < 8; q++) dst[p + 2 * q] = src[p + 2 * q];
    }
    __syncthreads();

    {
      int kk = tid >> 1, hh = (tid & 1) * 8;
      int ck = trow[qtr * 128 + kk];
      bool valid = (s < ck * 4);
      const float4* kr = reinterpret_cast<const float4*>(&Ks[kk][0]);
      float d[8];
#pragma unroll
      for (int h = 0; h < 8; h++) d[h] = 0.f;
#pragma unroll
      for (int c4 = 0; c4 < 16; c4++) {
        float4 kv = kr[c4];
#pragma unroll
        for (int h = 0; h < 8; h++) {
          float4 qv = qs4[(hh + h) * 16 + c4];
          d[h] += qv.x * kv.x + qv.y * kv.y + qv.z * kv.z + qv.w * kv.w;
        }
      }
#pragma unroll
      for (int h = 0; h < 8; h++) ew[hh + h][kk] = valid ? __expf(d[h] * 0.125f) : 0.f;
    }
    __syncthreads();

    {
      int h = tid >> 4, seg = tid & 15;
      float4 v0 = *reinterpret_cast<const float4*>(&ew[h][seg * 8]);
      float4 v1 = *reinterpret_cast<const float4*>(&ew[h][seg * 8 + 4]);
      float p = v0.x + v0.y + v0.z + v0.w + v1.x + v1.y + v1.z + v1.w;
#pragma unroll
      for (int off = 8; off > 0; off >>= 1) p += __shfl_down_sync(0xffffffffu, p, off);
      if (seg == 0) denom[h] += p;
    }

    for (int k4 = 0; k4 < 128; k4 += 4) {
      float4 e0 = *reinterpret_cast<const float4*>(&ew[g][k4]);
      float4 e1 = *reinterpret_cast<const float4*>(&ew[g + 4][k4]);
      float4 e2 = *reinterpret_cast<const float4*>(&ew[g + 8][k4]);
      float4 e3 = *reinterpret_cast<const float4*>(&ew[g + 12][k4]);
      float kv0 = Ks[k4 + 0][c];
      float kv1 = Ks[k4 + 1][c];
      float kv2 = Ks[k4 + 2][c];
      float kv3 = Ks[k4 + 3][c];
      acc0 += e0.x * kv0 + e0.y * kv1 + e0.z * kv2 + e0.w * kv3;
      acc1 += e1.x * kv0 + e1.y * kv1 + e1.z * kv2 + e1.w * kv3;
      acc2 += e2.x * kv0 + e2.y * kv1 + e2.z * kv2 + e2.w * kv3;
      acc3 += e3.x * kv0 + e3.y * kv1 + e3.z * kv2 + e3.w * kv3;
    }
  }
  __syncthreads();

  g_ao[(size_t)s * 1024 + (g) * 64 + c] = acc0 / denom[g];
  g_ao[(size_t)s * 1024 + (g + 4) * 64 + c] = acc1 / denom[g + 4];
  g_ao[(size_t)s * 1024 + (g + 8) * 64 + c] = acc2 / denom[g + 8];
  g_ao[(size_t)s * 1024 + (g + 12) * 64 + c] = acc3 / denom[g + 12];
}

// ---------------------------- launcher ----------------------------------
extern "C" void kernel_launch(void* const* d_in, const int* in_sizes, int n_in,
                              void* d_out, int out_size) {
  (void)in_sizes; (void)n_in; (void)out_size;
  const float* x      = (const float*)d_in[0];
  const float* w_kva  = (const float*)d_in[1];
  const float* w_kvb  = (const float*)d_in[2];
  const float* w_za   = (const float*)d_in[3];
  const float* w_zb   = (const float*)d_in[4];
  const float* b_a    = (const float*)d_in[5];
  const float* b_b    = (const float*)d_in[6];
  const float* w_dq   = (const float*)d_in[7];
  const float* w_iuq  = (const float*)d_in[8];
  const float* w_w    = (const float*)d_in[9];
  const float* w_k    = (const float*)d_in[10];
  const float* w_uq   = (const float*)d_in[11];
  const float* o_down = (const float*)d_in[12];
  const float* o_up   = (const float*)d_in[13];
  const float* kvn_w  = (const float*)d_in[14];
  const float* kvn_b  = (const float*)d_in[15];
  const float* qn_w   = (const float*)d_in[16];
  const float* qn_b   = (const float*)d_in[17];
  const float* sink   = (const float*)d_in[18];
  float* out = (float*)d_out;

  void *p_cz, *p_cq, *p_qi, *p_kp, *p_qf, *p_ao, *p_gb;
  cudaGetSymbolAddress(&p_cz, g_cz);
  cudaGetSymbolAddress(&p_cq, g_cq);
  cudaGetSymbolAddress(&p_qi, g_qi);
  cudaGetSymbolAddress(&p_kp, g_kp);
  cudaGetSymbolAddress(&p_qf, g_qf);
  cudaGetSymbolAddress(&p_ao, g_ao);
  cudaGetSymbolAddress(&p_gb, g_gb);

  // fuse the 4 narrow projection weights into one [2048,256] matrix
  concatw_kernel<<<(D_DIM * C_DIM + 255) / 256, 256>>>(w_kva, w_kvb, w_za, w_zb);

  // superA: c_q (128) || fused c/z tensor GEMM (64) || k_proj (8) || hw (32)
  SuperAArgs sa;
  sa.x = x;
  sa.w_dq = w_dq;
  sa.w_k = w_k;
  sa.w_w = w_w;
  sa.cq = (float*)p_cq;
  sa.cz = (float*)p_cz;
  sa.kp = (float*)p_kp;
  superA_kernel<<<232, 256>>>(sa);

  // chunk compression + LN(kc)
  compress_kernel<<<NC_CH, 64>>>(b_a, b_b, kvn_w, kvn_b);

  // superC: q_i fp32 GEMM (64) || w_uq tensor GEMM (256)
  superC_kernel<<<320, 256>>>((const float*)p_cq, w_iuq, w_uq, (float*)p_qi, (float*)p_qf);

  // LN+rope on q; indexer scoring; exact top-k (half-sort + half-cleaner)
  qln_rope_kernel<<<S_LEN, dim3(64, 16)>>>(qn_w, qn_b);
  iscore_kernel<<<S_LEN, 256>>>();
  topk_kernel<<<S_LEN, 512>>>();

  // sparse attention over top-k compressed chunks
  attn_kernel<<<S_LEN, 256>>>(sink);

  // grouped o_down: batched tensor GEMM
  tgemm_kernel<<<dim3(DG_N / 128, S_LEN / 128, NG_N), 256>>>(
      (const float*)p_ao, o_down, (float*)p_gb,
      256, NH_N * C_DIM, DG_N, NG_N * DG_N,
      /*sA=*/256, /*sB=*/(long)256 * DG_N, /*sC=*/DG_N);

  // o_up (tensor)
  tgemm_kernel<<<dim3(D_DIM / 128, S_LEN / 128, 1), 256>>>(
      (const float*)p_gb, o_up, out,
      NG_N * DG_N, NG_N * DG_N, D_DIM, D_DIM, 0, 0, 0);
}

// round 17
// speedup vs baseline: 1.7970x; 1.1229x over previous
#include <cuda_runtime.h>
#include <cuda_bf16.h>
#include <cstdint>
#include <cstddef>

// ---------------- problem constants ----------------
#define S_LEN   4096
#define D_DIM   2048
#define C_DIM   64
#define NC_CH   1024
#define TOPK_N  512
#define NH_N    16
#define DC_N    512
#define NHI_N   4
#define CI_N    64
#define NG_N    4
#define DG_N    512

#define NEG_INF (__int_as_float(0xff800000))

// ---------------- scratch ----------------
__device__ float g_cz[S_LEN * 256];     // fused [c_a | c_b | z_a | z_b] per row
__device__ float g_wcz[D_DIM * 256];    // fused weights [w_kva|w_kvb|w_za|w_zb]
__device__ float g_wc[1024 * 2048];     // W_comb = blockdiag(o_down) @ o_up
__device__ float g_kc[NC_CH * C_DIM];
__device__ float g_cq[S_LEN * DC_N];
__device__ float g_qi[S_LEN * NHI_N * CI_N];
__device__ float g_hw[S_LEN * NHI_N];
__device__ float g_kp[NC_CH * CI_N];
__device__ float g_qf[S_LEN * NH_N * C_DIM];
__device__ float g_is[(size_t)S_LEN * NC_CH];
__device__ int   g_ti[S_LEN * TOPK_N];
__device__ float g_ao[S_LEN * NH_N * C_DIM];

// ---------------- bf16 helpers ----------------
__device__ __forceinline__ uint32_t pack_bf16(float e0, float e1) {
  uint32_t d;
  asm("cvt.rn.bf16x2.f32 %0, %1, %2;" : "=r"(d) : "f"(e1), "f"(e0));
  return d;
}
__device__ __forceinline__ void split_pair(float a0, float a1, uint32_t& hp, uint32_t& lp) {
  hp = pack_bf16(a0, a1);
  float r0 = a0 - __uint_as_float(hp << 16);
  float r1 = a1 - __uint_as_float(hp & 0xffff0000u);
  lp = pack_bf16(r0, r1);
}
__device__ __forceinline__ void mma_bf16(float* c, const uint32_t* a, const uint32_t* b) {
  asm volatile(
      "mma.sync.aligned.m16n8k16.row.col.f32.bf16.bf16.f32 "
      "{%0,%1,%2,%3}, {%4,%5,%6,%7}, {%8,%9}, {%0,%1,%2,%3};"
      : "+f"(c[0]), "+f"(c[1]), "+f"(c[2]), "+f"(c[3])
      : "r"(a[0]), "r"(a[1]), "r"(a[2]), "r"(a[3]), "r"(b[0]), "r"(b[1]));
}

// ================= fp32 SGEMM body (R4-exact arithmetic) ================
__device__ __forceinline__ void sgemm_body(
    char* sm, const float* A, const float* B, float* Cc,
    int K, int lda, int ldb, int ldc, int bm, int bn) {
  float (*As)[8][128] = reinterpret_cast<float(*)[8][128]>(sm);
  float (*Bs)[8][132] = reinterpret_cast<float(*)[8][132]>(sm + 8192);
  const int tid = threadIdx.x;
  const int tx = tid & 15, ty = tid >> 4;
  const int arow = tid >> 1, acol = (tid & 1) * 4;
  const int brow = tid >> 5, bcol = (tid & 31) * 4;

  const float* Aptr = A + (size_t)(bm + arow) * lda + acol;
  const float* Bptr = B + (size_t)brow * ldb + bn + bcol;

  float acc[8][8];
#pragma unroll
  for (int i = 0; i < 8; i++)
#pragma unroll
    for (int j = 0; j < 8; j++) acc[i][j] = 0.f;

  {
    float4 av = *reinterpret_cast<const float4*>(Aptr);
    float4 bv = *reinterpret_cast<const float4*>(Bptr);
    As[0][acol + 0][arow] = av.x;
    As[0][acol + 1][arow] = av.y;
    As[0][acol + 2][arow] = av.z;
    As[0][acol + 3][arow] = av.w;
    Bs[0][brow][bcol + 0] = bv.x;
    Bs[0][brow][bcol + 1] = bv.y;
    Bs[0][brow][bcol + 2] = bv.z;
    Bs[0][brow][bcol + 3] = bv.w;
  }
  __syncthreads();

  int buf = 0;
  for (int k0 = 0; k0 < K; k0 += 8) {
    float4 av, bv;
    const bool more = (k0 + 8 < K);
    if (more) {
      av = *reinterpret_cast<const float4*>(Aptr + k0 + 8);
      bv = *reinterpret_cast<const float4*>(Bptr + (size_t)(k0 + 8) * ldb);
    }
#pragma unroll
    for (int kk = 0; kk < 8; kk++) {
      float a[8], b[8];
#pragma unroll
      for (int i = 0; i < 8; i++) a[i] = As[buf][kk][ty * 8 + i];
#pragma unroll
      for (int j = 0; j < 8; j++) b[j] = Bs[buf][kk][tx * 8 + j];
#pragma unroll
      for (int i = 0; i < 8; i++)
#pragma unroll
        for (int j = 0; j < 8; j++) acc[i][j] += a[i] * b[j];
    }
    if (more) {
      int nb = buf ^ 1;
      As[nb][acol + 0][arow] = av.x;
      As[nb][acol + 1][arow] = av.y;
      As[nb][acol + 2][arow] = av.z;
      As[nb][acol + 3][arow] = av.w;
      Bs[nb][brow][bcol + 0] = bv.x;
      Bs[nb][brow][bcol + 1] = bv.y;
      Bs[nb][brow][bcol + 2] = bv.z;
      Bs[nb][brow][bcol + 3] = bv.w;
      __syncthreads();
      buf = nb;
    }
  }

#pragma unroll
  for (int i = 0; i < 8; i++) {
    float* crow = Cc + (size_t)(bm + ty * 8 + i) * ldc + bn + tx * 8;
    *reinterpret_cast<float4*>(crow) = make_float4(acc[i][0], acc[i][1], acc[i][2], acc[i][3]);
    *reinterpret_cast<float4*>(crow + 4) = make_float4(acc[i][4], acc[i][5], acc[i][6], acc[i][7]);
  }
}

// ================= proj64 body (fp32; used for k_proj w/ chunk-mean) ====
__device__ __forceinline__ float4 ld_mean4(const float* p) {
  float4 a = *reinterpret_cast<const float4*>(p);
  float4 b = *reinterpret_cast<const float4*>(p + D_DIM);
  float4 c = *reinterpret_cast<const float4*>(p + 2 * D_DIM);
  float4 d = *reinterpret_cast<const float4*>(p + 3 * D_DIM);
  return make_float4(0.25f * (((a.x + b.x) + c.x) + d.x),
                     0.25f * (((a.y + b.y) + c.y) + d.y),
                     0.25f * (((a.z + b.z) + c.z) + d.z),
                     0.25f * (((a.w + b.w) + c.w) + d.w));
}

__device__ __forceinline__ void proj64_body(
    char* sm, const float* A, const float* B, float* Cc, int bm, bool mean4) {
  float (*As)[128] = reinterpret_cast<float(*)[128]>(sm);
  float (*Bs)[68] = reinterpret_cast<float(*)[68]>(sm + 4096);
  const int tid = threadIdx.x;
  const int tx = tid & 15, ty = tid >> 4;
  const int arow = tid >> 1, acol = (tid & 1) * 4;
  const int brow = tid >> 4, bcol = (tid & 15) * 4;
  const bool bload = (tid < 128);

  const float* Aptr = mean4 ? (A + (size_t)(4 * (bm + arow)) * D_DIM + acol)
                            : (A + (size_t)(bm + arow) * D_DIM + acol);
  const float* Bptr = B + (size_t)brow * C_DIM + bcol;

  float acc[8][4];
#pragma unroll
  for (int i = 0; i < 8; i++)
#pragma unroll
    for (int j = 0; j < 4; j++) acc[i][j] = 0.f;

  float4 av = mean4 ? ld_mean4(Aptr) : *reinterpret_cast<const float4*>(Aptr);
  float4 bv = bload ? *reinterpret_cast<const float4*>(Bptr) : make_float4(0, 0, 0, 0);

  for (int k0 = 0; k0 < D_DIM; k0 += 8) {
    As[acol + 0][arow] = av.x;
    As[acol + 1][arow] = av.y;
    As[acol + 2][arow] = av.z;
    As[acol + 3][arow] = av.w;
    if (bload) {
      Bs[brow][bcol + 0] = bv.x;
      Bs[brow][bcol + 1] = bv.y;
      Bs[brow][bcol + 2] = bv.z;
      Bs[brow][bcol + 3] = bv.w;
    }
    __syncthreads();

    if (k0 + 8 < D_DIM) {
      av = mean4 ? ld_mean4(Aptr + k0 + 8) : *reinterpret_cast<const float4*>(Aptr + k0 + 8);
      if (bload) bv = *reinterpret_cast<const float4*>(Bptr + (size_t)(k0 + 8) * C_DIM);
    }

#pragma unroll
    for (int kk = 0; kk < 8; kk++) {
      float a[8], b[4];
#pragma unroll
      for (int i = 0; i < 8; i++) a[i] = As[kk][ty * 8 + i];
#pragma unroll
      for (int j = 0; j < 4; j++) b[j] = Bs[kk][tx * 4 + j];
#pragma unroll
      for (int i = 0; i < 8; i++)
#pragma unroll
        for (int j = 0; j < 4; j++) acc[i][j] += a[i] * b[j];
    }
    __syncthreads();
  }

#pragma unroll
  for (int i = 0; i < 8; i++) {
    float* crow = Cc + (size_t)(bm + ty * 8 + i) * C_DIM + tx * 4;
    *reinterpret_cast<float4*>(crow) = make_float4(acc[i][0], acc[i][1], acc[i][2], acc[i][3]);
  }
}

// ================= hw body =============================================
__device__ __forceinline__ void hw_body(const float* x, const float* w_w, int blk) {
  int warp_g = blk * 8 + (threadIdx.x >> 5);
  int lane = threadIdx.x & 31;
  const float4* wr = reinterpret_cast<const float4*>(w_w);
  for (int row = warp_g; row < S_LEN; row += 256) {
    const float4* xr = reinterpret_cast<const float4*>(x + (size_t)row * D_DIM);
    float d0 = 0.f, d1 = 0.f, d2 = 0.f, d3 = 0.f;
    for (int i = lane; i < D_DIM / 4; i += 32) {
      float4 xv = xr[i];
      float4 w0 = wr[i * 4 + 0];
      float4 w1 = wr[i * 4 + 1];
      float4 w2 = wr[i * 4 + 2];
      float4 w3 = wr[i * 4 + 3];
      d0 += xv.x * w0.x + xv.y * w1.x + xv.z * w2.x + xv.w * w3.x;
      d1 += xv.x * w0.y + xv.y * w1.y + xv.z * w2.y + xv.w * w3.y;
      d2 += xv.x * w0.z + xv.y * w1.z + xv.z * w2.z + xv.w * w3.z;
      d3 += xv.x * w0.w + xv.y * w1.w + xv.z * w2.w + xv.w * w3.w;
    }
#pragma unroll
    for (int off = 16; off > 0; off >>= 1) {
      d0 += __shfl_down_sync(0xffffffffu, d0, off);
      d1 += __shfl_down_sync(0xffffffffu, d1, off);
      d2 += __shfl_down_sync(0xffffffffu, d2, off);
      d3 += __shfl_down_sync(0xffffffffu, d3, off);
    }
    if (lane == 0) {
      g_hw[row * 4 + 0] = d0;
      g_hw[row * 4 + 1] = d1;
      g_hw[row * 4 + 2] = d2;
      g_hw[row * 4 + 3] = d3;
    }
  }
}

// ================= tensor GEMM body (R9 bf16 3-term) ===================
__device__ __forceinline__ void tgemm_body(
    char* sm, const float* A, const float* B, float* Cc,
    int K, int lda, int ldb, int ldc, int bm, int bn) {
  uint32_t* Ah = reinterpret_cast<uint32_t*>(sm);
  uint32_t* Al = reinterpret_cast<uint32_t*>(sm + 12288);
  uint32_t* Bh = reinterpret_cast<uint32_t*>(sm + 24576);
  uint32_t* Bl = reinterpret_cast<uint32_t*>(sm + 33280);
#define AH(b, r, p) Ah[(b) * 1536 + (r) * 12 + (p)]
#define AL(b, r, p) Al[(b) * 1536 + (r) * 12 + (p)]
#define BH(b, r, c) Bh[(b) * 1088 + (r) * 136 + (c)]
#define BL(b, r, c) Bl[(b) * 1088 + (r) * 136 + (c)]

  const int tid = threadIdx.x;
  const int warp = tid >> 5, lane = tid & 31;
  const int wm = warp >> 2, wn = warp & 3;
  const int g = lane >> 2, t = lane & 3;

  const int arow = tid >> 1, akoff = (tid & 1) * 8;
  const int brp = tid >> 5, bcol = lane * 4;

  const float* Aptr = A + (size_t)(bm + arow) * lda + akoff;
  const float* Bptr0 = B + (size_t)(2 * brp) * ldb + bn + bcol;
  const float* Bptr1 = Bptr0 + ldb;

  float acc[4][4][4];
#pragma unroll
  for (int i = 0; i < 4; i++)
#pragma unroll
    for (int j = 0; j < 4; j++)
#pragma unroll
      for (int r = 0; r < 4; r++) acc[i][j][r] = 0.f;

  float4 av0 = *reinterpret_cast<const float4*>(Aptr);
  float4 av1 = *reinterpret_cast<const float4*>(Aptr + 4);
  float4 bv0 = *reinterpret_cast<const float4*>(Bptr0);
  float4 bv1 = *reinterpret_cast<const float4*>(Bptr1);
  {
    uint32_t h[4], l[4];
    split_pair(av0.x, av0.y, h[0], l[0]);
    split_pair(av0.z, av0.w, h[1], l[1]);
    split_pair(av1.x, av1.y, h[2], l[2]);
    split_pair(av1.z, av1.w, h[3], l[3]);
    int ac = akoff >> 1;
    *reinterpret_cast<uint4*>(&AH(0, arow, ac)) = make_uint4(h[0], h[1], h[2], h[3]);
    *reinterpret_cast<uint4*>(&AL(0, arow, ac)) = make_uint4(l[0], l[1], l[2], l[3]);
    uint32_t bh[4], bl[4];
    split_pair(bv0.x, bv1.x, bh[0], bl[0]);
    split_pair(bv0.y, bv1.y, bh[1], bl[1]);
    split_pair(bv0.z, bv1.z, bh[2], bl[2]);
    split_pair(bv0.w, bv1.w, bh[3], bl[3]);
    *reinterpret_cast<uint4*>(&BH(0, brp, bcol)) = make_uint4(bh[0], bh[1], bh[2], bh[3]);
    *reinterpret_cast<uint4*>(&BL(0, brp, bcol)) = make_uint4(bl[0], bl[1], bl[2], bl[3]);
  }
  __syncthreads();

  int buf = 0;
  for (int k0 = 0; k0 < K; k0 += 16) {
    const bool more = (k0 + 16 < K);
    if (more) {
      av0 = *reinterpret_cast<const float4*>(Aptr + k0 + 16);
      av1 = *reinterpret_cast<const float4*>(Aptr + k0 + 20);
      bv0 = *reinterpret_cast<const float4*>(Bptr0 + (size_t)(k0 + 16) * ldb);
      bv1 = *reinterpret_cast<const float4*>(Bptr1 + (size_t)(k0 + 16) * ldb);
    }

    {
      uint32_t bhf[4][2], blf[4][2];
#pragma unroll
      for (int ni = 0; ni < 4; ni++) {
        int colB = wn * 32 + ni * 8 + g;
        bhf[ni][0] = BH(buf, t, colB);
        bhf[ni][1] = BH(buf, t + 4, colB);
        blf[ni][0] = BL(buf, t, colB);
        blf[ni][1] = BL(buf, t + 4, colB);
      }
#pragma unroll
      for (int mi = 0; mi < 4; mi++) {
        int rowA = wm * 64 + mi * 16 + g;
        uint32_t ah[4], al[4];
        ah[0] = AH(buf, rowA, t);
        ah[1] = AH(buf, rowA + 8, t);
        ah[2] = AH(buf, rowA, t + 4);
        ah[3] = AH(buf, rowA + 8, t + 4);
        al[0] = AL(buf, rowA, t);
        al[1] = AL(buf, rowA + 8, t);
        al[2] = AL(buf, rowA, t + 4);
        al[3] = AL(buf, rowA + 8, t + 4);
#pragma unroll
        for (int ni = 0; ni < 4; ni++) mma_bf16(acc[mi][ni], ah, bhf[ni]);
#pragma unroll
        for (int ni = 0; ni < 4; ni++) mma_bf16(acc[mi][ni], ah, blf[ni]);
#pragma unroll
        for (int ni = 0; ni < 4; ni++) mma_bf16(acc[mi][ni], al, bhf[ni]);
      }
    }

    if (more) {
      int nb = buf ^ 1;
      uint32_t h[4], l[4];
      split_pair(av0.x, av0.y, h[0], l[0]);
      split_pair(av0.z, av0.w, h[1], l[1]);
      split_pair(av1.x, av1.y, h[2], l[2]);
      split_pair(av1.z, av1.w, h[3], l[3]);
      int ac = akoff >> 1;
      *reinterpret_cast<uint4*>(&AH(nb, arow, ac)) = make_uint4(h[0], h[1], h[2], h[3]);
      *reinterpret_cast<uint4*>(&AL(nb, arow, ac)) = make_uint4(l[0], l[1], l[2], l[3]);
      uint32_t bh[4], bl[4];
      split_pair(bv0.x, bv1.x, bh[0], bl[0]);
      split_pair(bv0.y, bv1.y, bh[1], bl[1]);
      split_pair(bv0.z, bv1.z, bh[2], bl[2]);
      split_pair(bv0.w, bv1.w, bh[3], bl[3]);
      *reinterpret_cast<uint4*>(&BH(nb, brp, bcol)) = make_uint4(bh[0], bh[1], bh[2], bh[3]);
      *reinterpret_cast<uint4*>(&BL(nb, brp, bcol)) = make_uint4(bl[0], bl[1], bl[2], bl[3]);
      __syncthreads();
      buf = nb;
    }
  }

#pragma unroll
  for (int mi = 0; mi < 4; mi++) {
    int row0 = bm + wm * 64 + mi * 16 + g;
#pragma unroll
    for (int ni = 0; ni < 4; ni++) {
      int col = bn + wn * 32 + ni * 8 + 2 * t;
      *reinterpret_cast<float2*>(Cc + (size_t)row0 * ldc + col) =
          make_float2(acc[mi][ni][0], acc[mi][ni][1]);
      *reinterpret_cast<float2*>(Cc + (size_t)(row0 + 8) * ldc + col) =
          make_float2(acc[mi][ni][2], acc[mi][ni][3]);
    }
  }
#undef AH
#undef AL
#undef BH
#undef BL
}

__global__ __launch_bounds__(256) void tgemm_kernel(
    const float* __restrict__ A, const float* __restrict__ B,
    float* __restrict__ Cc, int K, int lda, int ldb, int ldc,
    long sA, long sB, long sC) {
  __shared__ __align__(16) char sm[41984];
  tgemm_body(sm, A + (long)blockIdx.z * sA, B + (long)blockIdx.z * sB,
             Cc + (long)blockIdx.z * sC, K, lda, ldb, ldc,
             blockIdx.y * 128, blockIdx.x * 128);
}

// ======= weight concat: [w_kva|w_kvb|w_za|w_zb] -> g_wcz [2048][256] ====
__global__ void concatw_kernel(const float* __restrict__ wa, const float* __restrict__ wb,
                               const float* __restrict__ wza, const float* __restrict__ wzb) {
  int idx = blockIdx.x * 256 + threadIdx.x;
  if (idx >= D_DIM * C_DIM) return;
  int r = idx >> 6, c = idx & 63;
  g_wcz[r * 256 + c] = wa[idx];
  g_wcz[r * 256 + 64 + c] = wb[idx];
  g_wcz[r * 256 + 128 + c] = wza[idx];
  g_wcz[r * 256 + 192 + c] = wzb[idx];
}

// ================= superA ==============================================
struct SuperAArgs {
  const float* x;
  const float* w_dq;
  const float* w_k;
  const float* w_w;
  float* cq;
  float* cz;
  float* kp;
};

__global__ __launch_bounds__(256) void superA_kernel(SuperAArgs a) {
  __shared__ __align__(16) char sm[41984];
  int id = blockIdx.x;
  if (id < 128) {
    sgemm_body(sm, a.x, a.w_dq, a.cq, D_DIM, D_DIM, DC_N, DC_N,
               (id >> 2) * 128, (id & 3) * 128);
  } else if (id < 192) {
    int pid = id - 128;  // 64 blocks: 32 row tiles x 2 col tiles
    tgemm_body(sm, a.x, g_wcz, a.cz, D_DIM, D_DIM, 256, 256,
               (pid >> 1) * 128, (pid & 1) * 128);
  } else if (id < 200) {
    proj64_body(sm, a.x, a.w_k, a.kp, (id - 192) * 128, true);
  } else {
    hw_body(a.x, a.w_w, id - 200);
  }
}

// ====== superC: q_i fp32 GEMM || w_uq tensor GEMM || W_comb precompute ==
// blocks [0,64): q_i | [64,320): w_uq | [320,448): W_comb (4 groups x 32)
__global__ __launch_bounds__(256) void superC_kernel(
    const float* __restrict__ cq, const float* __restrict__ w_iuq,
    const float* __restrict__ w_uq, float* __restrict__ qi, float* __restrict__ qf,
    const float* __restrict__ o_down, const float* __restrict__ o_up) {
  __shared__ __align__(16) char sm[41984];
  int id = blockIdx.x;
  if (id < 64) {
    sgemm_body(sm, cq, w_iuq, qi, DC_N, DC_N, NHI_N * CI_N, NHI_N * CI_N,
               (id >> 1) * 128, (id & 1) * 128);
  } else if (id < 320) {
    int tid2 = id - 64;
    tgemm_body(sm, cq, w_uq, qf, DC_N, DC_N, NH_N * C_DIM, NH_N * C_DIM,
               (tid2 >> 3) * 128, (tid2 & 7) * 128);
  } else {
    // W_comb[g*256+d, j] = sum_e o_down[g,d,e] * o_up[g*512+e, j]
    int id2 = id - 320;
    int grp = id2 >> 5, rem = id2 & 31;       // 4 groups x (2 row x 16 col)
    int bm = (rem >> 4) * 128, bn = (rem & 15) * 128;
    tgemm_body(sm, o_down + (size_t)grp * 256 * DG_N,
               o_up + (size_t)grp * DG_N * D_DIM,
               g_wc + (size_t)grp * 256 * D_DIM,
               /*K=*/DG_N, /*lda=*/DG_N, /*ldb=*/D_DIM, /*ldc=*/D_DIM, bm, bn);
  }
}

// ------------- compression softmax + LayerNorm (reads fused g_cz) -------
__global__ void compress_kernel(const float* __restrict__ b_a,
                                const float* __restrict__ b_b,
                                const float* __restrict__ kvn_w,
                                const float* __restrict__ kvn_b) {
  int nc = blockIdx.x;
  int c = threadIdx.x;  // 64
  float lg[8], val[8];
#pragma unroll
  for (int m = 0; m < 4; m++) {
    int cur = (nc * 4 + m) * 256;
    lg[4 + m] = g_cz[cur + 128 + c] + b_a[m * 64 + c];   // z_a
    val[4 + m] = g_cz[cur + c];                          // c_a
    if (nc > 0) {
      int prev = ((nc - 1) * 4 + m) * 256;
      lg[m] = g_cz[prev + 192 + c] + b_b[m * 64 + c];    // z_b
      val[m] = g_cz[prev + 64 + c];                      // c_b
    } else {
      lg[m] = -1e30f + b_b[m * 64 + c];
      val[m] = 0.f;
    }
  }
  float mx = lg[0];
#pragma unroll
  for (int i = 1; i < 8; i++) mx = fmaxf(mx, lg[i]);
  float se = 0.f, comp = 0.f;
#pragma unroll
  for (int i = 0; i < 8; i++) {
    float e = expf(lg[i] - mx);
    se += e;
    comp += e * val[i];
  }
  comp /= se;

  __shared__ float red[64];
  red[c] = comp;
  __syncthreads();
  for (int off = 32; off > 0; off >>= 1) {
    if (c < off) red[c] += red[c + off];
    __syncthreads();
  }
  float mu = red[0] * (1.f / 64.f);
  __syncthreads();
  float dv = comp - mu;
  red[c] = dv * dv;
  __syncthreads();
  for (int off = 32; off > 0; off >>= 1) {
    if (c < off) red[c] += red[c + off];
    __syncthreads();
  }
  float var = red[0] * (1.f / 64.f);
  g_kc[nc * 64 + c] = dv * rsqrtf(var + 1e-6f) * kvn_w[c] + kvn_b[c];
}

// ------------- per-(s,h) LayerNorm then RoPE ----------------------------
__global__ void qln_rope_kernel(const float* __restrict__ qn_w,
                                const float* __restrict__ qn_b) {
  int s = blockIdx.x;
  int c = threadIdx.x;  // 64
  int h = threadIdx.y;  // 16
  float v = g_qf[(size_t)s * 1024 + h * 64 + c];
  __shared__ float red[16][64];
  __shared__ float lnb[16][65];
  red[h][c] = v;
  __syncthreads();
  for (int off = 32; off > 0; off >>= 1) {
    if (c < off) red[h][c] += red[h][c + off];
    __syncthreads();
  }
  float mu = red[h][0] * (1.f / 64.f);
  __syncthreads();
  float dv = v - mu;
  red[h][c] = dv * dv;
  __syncthreads();
  for (int off = 32; off > 0; off >>= 1) {
    if (c < off) red[h][c] += red[h][c + off];
    __syncthreads();
  }
  float var = red[h][0] * (1.f / 64.f);
  float ln = dv * rsqrtf(var + 1e-6f) * qn_w[c] + qn_b[c];
  lnb[h][c] = ln;
  __syncthreads();
  float outv;
  if (c < 32) {
    outv = ln;
  } else {
    int j = (c - 32) >> 1;
    float inv = exp2f(-(float)j * 0.830482023722f);  // 10000^(-j/16)
    float ang = (float)s * inv;
    float cs = cosf(ang), sn = sinf(ang);
    float x0 = lnb[h][32 + 2 * j], x1 = lnb[h][32 + 2 * j + 1];
    outv = ((c & 1) == 0) ? (x0 * cs - x1 * sn) : (x0 * sn + x1 * cs);
  }
  g_qf[(size_t)s * 1024 + h * 64 + c] = outv;
}

// ------------- indexer scores (R12 verbatim: 256 thr, 4 chunks/thr) -----
__global__ void iscore_kernel() {
  int s = blockIdx.x;
  __shared__ float qs[256];
  __shared__ float ws[4];
  int tid = threadIdx.x;  // 256
  qs[tid] = g_qi[(size_t)s * 256 + tid];
  if (tid < 4) ws[tid] = g_hw[s * 4 + tid];
  __syncthreads();
  const float4* qs4 = reinterpret_cast<const float4*>(qs);
  for (int k = tid; k < NC_CH; k += 256) {
    const float4* kr = reinterpret_cast<const float4*>(g_kp + k * 64);
    float d0 = 0.f, d1 = 0.f, d2 = 0.f, d3 = 0.f;
#pragma unroll
    for (int c4 = 0; c4 < 16; c4++) {
      float4 kv = kr[c4];
      float4 q0 = qs4[c4];
      float4 q1 = qs4[16 + c4];
      float4 q2 = qs4[32 + c4];
      float4 q3 = qs4[48 + c4];
      d0 += q0.x * kv.x + q0.y * kv.y + q0.z * kv.z + q0.w * kv.w;
      d1 += q1.x * kv.x + q1.y * kv.y + q1.z * kv.z + q1.w * kv.w;
      d2 += q2.x * kv.x + q2.y * kv.y + q2.z * kv.z + q2.w * kv.w;
      d3 += q3.x * kv.x + q3.y * kv.y + q3.z * kv.z + q3.w * kv.w;
    }
    float sc = fmaxf(d0, 0.f) * ws[0] + fmaxf(d1, 0.f) * ws[1] +
               fmaxf(d2, 0.f) * ws[2] + fmaxf(d3, 0.f) * ws[3];
    g_is[(size_t)s * NC_CH + k] = (k < s) ? sc : NEG_INF;
  }
}

// ------------- exact top-512: packed u64 half-sort + half-cleaner -------
__global__ __launch_bounds__(512) void topk_kernel() {
  int s = blockIdx.x, tid = threadIdx.x;  // 512
  __shared__ unsigned long long kv[1024];
#pragma unroll
  for (int i = 0; i < 2; i++) {
    int k = tid + 512 * i;
    uint32_t b = __float_as_uint(g_is[(size_t)s * 1024 + k]);
    uint32_t m = (b & 0x80000000u) ? ~b : (b | 0x80000000u);
    kv[k] = ((unsigned long long)m << 32) | (unsigned)(1023 - k);
  }
  __syncthreads();
  for (int k = 2; k <= 512; k <<= 1) {
    for (int j = k >> 1; j > 0; j >>= 1) {
#pragma unroll
      for (int w = 0; w < 2; w++) {
        int t = tid + 512 * w;
        int p = t ^ j;
        if (p > t) {
          unsigned long long a = kv[t], b2 = kv[p];
          bool before = (a > b2);
          bool dir = ((t & k) == 0);
          if (before != dir) {
            kv[t] = b2;
            kv[p] = a;
          }
        }
      }
      __syncthreads();
    }
  }
  unsigned long long a = kv[tid], b2 = kv[tid + 512];
  unsigned long long best = (a > b2) ? a : b2;
  g_ti[(size_t)s * 512 + tid] = 1023 - (int)(unsigned)(best & 0xffffffffu);
}

// ------------- gathered sparse attention (R12 verbatim, 256 thr) --------
__global__ __launch_bounds__(256) void attn_kernel(const float* __restrict__ sink) {
  const int s = blockIdx.x, tid = threadIdx.x;  // 256
  __shared__ float qs[1024];
  __shared__ float Ks[128][68];
  __shared__ float ew[16][128];
  __shared__ float denom[16];

#pragma unroll
  for (int i = 0; i < 4; i++) qs[tid + 256 * i] = g_qf[(size_t)s * 1024 + tid + 256 * i];
  if (tid < 16) denom[tid] = __expf(sink[tid]);
  __syncthreads();

  const int c = tid & 63, g = tid >> 6;
  float acc0 = 0.f, acc1 = 0.f, acc2 = 0.f, acc3 = 0.f;
  const float4* qs4 = reinterpret_cast<const float4*>(qs);
  const int* trow = g_ti + (size_t)s * 512;

  for (int qtr = 0; qtr < 4; qtr++) {
    if (qtr) __syncthreads();

    {
      int j = tid >> 1, p = tid & 1;
      int ck = trow[qtr * 128 + j];
      const float4* src = reinterpret_cast<const float4*>(g_kc + ck * 64);
      float4* dst = reinterpret_cast<float4*>(&Ks[j][0]);
#pragma unroll
      for (int q = 0; q < 8; q++) dst[p + 2 * q] = src[p + 2 * q];
    }
    __syncthreads();

    {
      int kk = tid >> 1, hh = (tid & 1) * 8;
      int ck = trow[qtr * 128 + kk];
      bool valid = (s < ck * 4);
      const float4* kr = reinterpret_cast<const float4*>(&Ks[kk][0]);
      float d[8];
#pragma unroll
      for (int h = 0; h < 8; h++) d[h] = 0.f;
#pragma unroll
      for (int c4 = 0; c4 < 16; c4++) {
        float4 kv = kr[c4];
#pragma unroll
        for (int h = 0; h < 8; h++) {
          float4 qv = qs4[(hh + h) * 16 + c4];
          d[h] += qv.x * kv.x + qv.y * kv.y + qv.z * kv.z + qv.w * kv.w;
        }
      }
#pragma unroll
      for (int h = 0; h < 8; h++) ew[hh + h][kk] = valid ? __expf(d[h] * 0.125f) : 0.f;
    }
    __syncthreads();

    {
      int h = tid >> 4, seg = tid & 15;
      float4 v0 = *reinterpret_cast<const float4*>(&ew[h][seg * 8]);
      float4 v1 = *reinterpret_cast<const float4*>(&ew[h][seg * 8 + 4]);
      float p = v0.x + v0.y + v0.z + v0.w + v1.x + v1.y + v1.z + v1.w;
#pragma unroll
      for (int off = 8; off > 0; off >>= 1) p += __shfl_down_sync(0xffffffffu, p, off);
      if (seg == 0) denom[h] += p;
    }

    for (int k4 = 0; k4 < 128; k4 += 4) {
      float4 e0 = *reinterpret_cast<const float4*>(&ew[g][k4]);
      float4 e1 = *reinterpret_cast<const float4*>(&ew[g + 4][k4]);
      float4 e2 = *reinterpret_cast<const float4*>(&ew[g + 8][k4]);
      float4 e3 = *reinterpret_cast<const float4*>(&ew[g + 12][k4]);
      float kv0 = Ks[k4 + 0][c];
      float kv1 = Ks[k4 + 1][c];
      float kv2 = Ks[k4 + 2][c];
      float kv3 = Ks[k4 + 3][c];
      acc0 += e0.x * kv0 + e0.y * kv1 + e0.z * kv2 + e0.w * kv3;
      acc1 += e1.x * kv0 + e1.y * kv1 + e1.z * kv2 + e1.w * kv3;
      acc2 += e2.x * kv0 + e2.y * kv1 + e2.z * kv2 + e2.w * kv3;
      acc3 += e3.x * kv0 + e3.y * kv1 + e3.z * kv2 + e3.w * kv3;
    }
  }
  __syncthreads();

  g_ao[(size_t)s * 1024 + (g) * 64 + c] = acc0 / denom[g];
  g_ao[(size_t)s * 1024 + (g + 4) * 64 + c] = acc1 / denom[g + 4];
  g_ao[(size_t)s * 1024 + (g + 8) * 64 + c] = acc2 / denom[g + 8];
  g_ao[(size_t)s * 1024 + (g + 12) * 64 + c] = acc3 / denom[g + 12];
}

// ---------------------------- launcher ----------------------------------
extern "C" void kernel_launch(void* const* d_in, const int* in_sizes, int n_in,
                              void* d_out, int out_size) {
  (void)in_sizes; (void)n_in; (void)out_size;
  const float* x      = (const float*)d_in[0];
  const float* w_kva  = (const float*)d_in[1];
  const float* w_kvb  = (const float*)d_in[2];
  const float* w_za   = (const float*)d_in[3];
  const float* w_zb   = (const float*)d_in[4];
  const float* b_a    = (const float*)d_in[5];
  const float* b_b    = (const float*)d_in[6];
  const float* w_dq   = (const float*)d_in[7];
  const float* w_iuq  = (const float*)d_in[8];
  const float* w_w    = (const float*)d_in[9];
  const float* w_k    = (const float*)d_in[10];
  const float* w_uq   = (const float*)d_in[11];
  const float* o_down = (const float*)d_in[12];
  const float* o_up   = (const float*)d_in[13];
  const float* kvn_w  = (const float*)d_in[14];
  const float* kvn_b  = (const float*)d_in[15];
  const float* qn_w   = (const float*)d_in[16];
  const float* qn_b   = (const float*)d_in[17];
  const float* sink   = (const float*)d_in[18];
  float* out = (float*)d_out;

  void *p_cz, *p_cq, *p_qi, *p_kp, *p_qf, *p_ao, *p_wc;
  cudaGetSymbolAddress(&p_cz, g_cz);
  cudaGetSymbolAddress(&p_cq, g_cq);
  cudaGetSymbolAddress(&p_qi, g_qi);
  cudaGetSymbolAddress(&p_kp, g_kp);
  cudaGetSymbolAddress(&p_qf, g_qf);
  cudaGetSymbolAddress(&p_ao, g_ao);
  cudaGetSymbolAddress(&p_wc, g_wc);

  // fuse the 4 narrow projection weights into one [2048,256] matrix
  concatw_kernel<<<(D_DIM * C_DIM + 255) / 256, 256>>>(w_kva, w_kvb, w_za, w_zb);

  // superA: c_q (128) || fused c/z tensor GEMM (64) || k_proj (8) || hw (32)
  SuperAArgs sa;
  sa.x = x;
  sa.w_dq = w_dq;
  sa.w_k = w_k;
  sa.w_w = w_w;
  sa.cq = (float*)p_cq;
  sa.cz = (float*)p_cz;
  sa.kp = (float*)p_kp;
  superA_kernel<<<232, 256>>>(sa);

  // chunk compression + LN(kc)
  compress_kernel<<<NC_CH, 64>>>(b_a, b_b, kvn_w, kvn_b);

  // superC: q_i fp32 (64) || w_uq tensor (256) || W_comb precompute (128)
  superC_kernel<<<448, 256>>>((const float*)p_cq, w_iuq, w_uq, (float*)p_qi, (float*)p_qf,
                              o_down, o_up);

  // LN+rope on q; indexer scoring; exact top-k (half-sort + half-cleaner)
  qln_rope_kernel<<<S_LEN, dim3(64, 16)>>>(qn_w, qn_b);
  iscore_kernel<<<S_LEN, 256>>>();
  topk_kernel<<<S_LEN, 512>>>();

  // sparse attention over top-k compressed chunks
  attn_kernel<<<S_LEN, 256>>>(sink);

  // fused epilogue: out = ao @ W_comb  (4096 x 2048, K=1024)
  tgemm_kernel<<<dim3(D_DIM / 128, S_LEN / 128, 1), 256>>>(
      (const float*)p_ao, (const float*)p_wc, out,
      /*K=*/1024, /*lda=*/1024, /*ldb=*/D_DIM, /*ldc=*/D_DIM, 0, 0, 0);
}